// round 2
// baseline (speedup 1.0000x reference)
#include <cuda_runtime.h>
#include <math.h>

#define NND 50000
#define HDIM 128

// Scratch (device globals — allocation-free contract)
__device__ int   g_deg[NND];
__device__ float g_dinv[NND];
__device__ float g_h[(size_t)NND * HDIM];
__device__ float g_agg[(size_t)NND * HDIM];
__device__ float g_feat[(size_t)NND * HDIM];

// ---------------- degree / norm ----------------
__global__ void deg_init_kernel(int n) {
    int i = blockIdx.x * blockDim.x + threadIdx.x;
    if (i < n) g_deg[i] = 1;  // self-loop
}

__global__ void deg_count_kernel(const int* __restrict__ dst, int E) {
    for (int e = blockIdx.x * blockDim.x + threadIdx.x; e < E;
         e += gridDim.x * blockDim.x)
        atomicAdd(&g_deg[dst[e]], 1);
}

__global__ void dinv_kernel(int n) {
    int i = blockIdx.x * blockDim.x + threadIdx.x;
    if (i < n) g_dinv[i] = rsqrtf((float)g_deg[i]);
}

// ---------------- SGEMM: H = (X @ W) * dinv[row]; AGG = H (self-loop init) ----
// X: [M, K] row-major, W: [K, 128] row-major. BM=64, BN=128, BK=8, TM=8, TN=4.
template <int K>
__global__ __launch_bounds__(256) void gemm_scale_kernel(
    const float* __restrict__ X, const float* __restrict__ W,
    float* __restrict__ H, float* __restrict__ AGG,
    const float* __restrict__ dinv, int M)
{
    __shared__ float As[8][64];
    __shared__ float Bs[8][HDIM];

    const int tid = threadIdx.x;
    const int tx  = tid & 31;   // 32 col-groups * 4 cols
    const int ty  = tid >> 5;   // 8 row-groups * 8 rows
    const int m0  = blockIdx.x * 64;

    float acc[8][4];
#pragma unroll
    for (int r = 0; r < 8; r++)
#pragma unroll
        for (int c = 0; c < 4; c++) acc[r][c] = 0.f;

    for (int k0 = 0; k0 < K; k0 += 8) {
        // load A tile (64x8) -> As[k][m]
#pragma unroll
        for (int i = 0; i < 2; i++) {
            int idx = tid + i * 256;       // 0..511
            int m = idx >> 3, k = idx & 7;
            int row = m0 + m;
            As[k][m] = (row < M) ? X[row * K + k0 + k] : 0.f;
        }
        // load B tile (8x128) -> Bs, float4 per thread
        {
            int idx = tid << 2;            // 0..1020
            int k = idx >> 7, j = idx & 127;
            float4 w = *(const float4*)&W[(k0 + k) * HDIM + j];
            *(float4*)&Bs[k][j] = w;
        }
        __syncthreads();

#pragma unroll
        for (int k = 0; k < 8; k++) {
            float4 a0 = *(const float4*)&As[k][ty * 8];
            float4 a1 = *(const float4*)&As[k][ty * 8 + 4];
            float4 bv = *(const float4*)&Bs[k][tx * 4];
            float a[8] = {a0.x, a0.y, a0.z, a0.w, a1.x, a1.y, a1.z, a1.w};
            float b[4] = {bv.x, bv.y, bv.z, bv.w};
#pragma unroll
            for (int r = 0; r < 8; r++)
#pragma unroll
                for (int c = 0; c < 4; c++) acc[r][c] += a[r] * b[c];
        }
        __syncthreads();
    }

#pragma unroll
    for (int r = 0; r < 8; r++) {
        int row = m0 + ty * 8 + r;
        if (row < M) {
            float s = dinv[row];
            float4 v = make_float4(acc[r][0] * s, acc[r][1] * s,
                                   acc[r][2] * s, acc[r][3] * s);
            int off = row * HDIM + tx * 4;
            *(float4*)&H[off]   = v;
            *(float4*)&AGG[off] = v;
        }
    }
}

// ---------------- edge scatter: AGG[dst] += H[src], 1 warp/edge --------------
__global__ __launch_bounds__(256) void scatter_kernel(
    const float* __restrict__ H, float* __restrict__ AGG,
    const int* __restrict__ src, const int* __restrict__ dst, int E)
{
    int gw   = (blockIdx.x * blockDim.x + threadIdx.x) >> 5;
    int lane = threadIdx.x & 31;
    if (gw >= E) return;
    int s = src[gw], d = dst[gw];
    float4 v = *(const float4*)&H[s * HDIM + lane * 4];
    float* p = &AGG[d * HDIM + lane * 4];
    asm volatile("red.global.add.v4.f32 [%0], {%1,%2,%3,%4};" ::
                 "l"(p), "f"(v.x), "f"(v.y), "f"(v.z), "f"(v.w) : "memory");
}

// ---------------- finalize: OUT = relu?(AGG*dinv[row] + b) -------------------
__global__ __launch_bounds__(256) void finalize_kernel(
    const float* __restrict__ AGG, const float* __restrict__ dinv,
    const float* __restrict__ bias, float* __restrict__ OUT,
    int M, int do_relu)
{
    int idx = blockIdx.x * blockDim.x + threadIdx.x;  // float4 index
    if (idx >= M * 32) return;
    int row = idx >> 5;
    int c4  = (idx & 31) * 4;
    float s = dinv[row];
    float4 v  = *(const float4*)&AGG[row * HDIM + c4];
    float4 bb = *(const float4*)&bias[c4];
    v.x = v.x * s + bb.x; v.y = v.y * s + bb.y;
    v.z = v.z * s + bb.z; v.w = v.w * s + bb.w;
    if (do_relu) {
        v.x = fmaxf(v.x, 0.f); v.y = fmaxf(v.y, 0.f);
        v.z = fmaxf(v.z, 0.f); v.w = fmaxf(v.w, 0.f);
    }
    *(float4*)&OUT[row * HDIM + c4] = v;
}

// ---------------- decode: logits[e] = dot(Z[a], Z[b]), 1 warp/edge -----------
__global__ __launch_bounds__(256) void decode_kernel(
    const float* __restrict__ Z, const int* __restrict__ ea,
    const int* __restrict__ eb, float* __restrict__ out, int EL)
{
    int gw   = (blockIdx.x * blockDim.x + threadIdx.x) >> 5;
    int lane = threadIdx.x & 31;
    if (gw >= EL) return;
    int i = ea[gw], j = eb[gw];
    float4 u = *(const float4*)&Z[i * HDIM + lane * 4];
    float4 v = *(const float4*)&Z[j * HDIM + lane * 4];
    float p = u.x * v.x + u.y * v.y + u.z * v.z + u.w * v.w;
#pragma unroll
    for (int o = 16; o; o >>= 1) p += __shfl_xor_sync(0xffffffffu, p, o);
    if (lane == 0) out[gw] = p;
}

extern "C" void kernel_launch(void* const* d_in, const int* in_sizes, int n_in,
                              void* d_out, int out_size)
{
    const float* x   = (const float*)d_in[0];
    const int*   ei  = (const int*)d_in[1];
    const int*   eli = (const int*)d_in[2];
    const float* W0  = (const float*)d_in[3];
    const float* b0  = (const float*)d_in[4];
    const float* W1  = (const float*)d_in[5];
    const float* b1  = (const float*)d_in[6];
    const float* W2  = (const float*)d_in[7];
    const float* b2  = (const float*)d_in[8];
    float* logits = (float*)d_out;

    const int N  = in_sizes[0] / 256;   // 50000
    const int E  = in_sizes[1] / 2;     // 320000
    const int EL = in_sizes[2] / 2;     // 200000
    const int* src = ei;
    const int* dst = ei + E;
    const int* la  = eli;
    const int* lb  = eli + EL;

    float *p_h, *p_agg, *p_feat, *p_dinv;
    cudaGetSymbolAddress((void**)&p_h,    g_h);
    cudaGetSymbolAddress((void**)&p_agg,  g_agg);
    cudaGetSymbolAddress((void**)&p_feat, g_feat);
    cudaGetSymbolAddress((void**)&p_dinv, g_dinv);

    const int TB = 256;
    // degrees + normalization
    deg_init_kernel<<<(N + TB - 1) / TB, TB>>>(N);
    deg_count_kernel<<<512, TB>>>(dst, E);
    dinv_kernel<<<(N + TB - 1) / TB, TB>>>(N);

    const int gemm_blocks = (N + 63) / 64;
    const int scat_blocks = (E + 7) / 8;          // 8 warps/block
    const int fin_blocks  = (N * 32 + TB - 1) / TB;

    // Layer 0: x[*,256] @ W0 -> relu
    gemm_scale_kernel<256><<<gemm_blocks, TB>>>(x, W0, p_h, p_agg, p_dinv, N);
    scatter_kernel<<<scat_blocks, TB>>>(p_h, p_agg, src, dst, E);
    finalize_kernel<<<fin_blocks, TB>>>(p_agg, p_dinv, b0, p_feat, N, 1);

    // Layer 1
    gemm_scale_kernel<128><<<gemm_blocks, TB>>>(p_feat, W1, p_h, p_agg, p_dinv, N);
    scatter_kernel<<<scat_blocks, TB>>>(p_h, p_agg, src, dst, E);
    finalize_kernel<<<fin_blocks, TB>>>(p_agg, p_dinv, b1, p_feat, N, 1);

    // Layer 2 (no relu)
    gemm_scale_kernel<128><<<gemm_blocks, TB>>>(p_feat, W2, p_h, p_agg, p_dinv, N);
    scatter_kernel<<<scat_blocks, TB>>>(p_h, p_agg, src, dst, E);
    finalize_kernel<<<fin_blocks, TB>>>(p_agg, p_dinv, b2, p_feat, N, 0);

    // Decode
    decode_kernel<<<(EL + 7) / 8, TB>>>(p_feat, la, lb, logits, EL);
}

// round 7
// speedup vs baseline: 1.1481x; 1.1481x over previous
#include <cuda_runtime.h>
#include <cuda_bf16.h>
#include <math.h>
#include <stdint.h>

#define NND 50000
#define HDIM 128

// ---------------- scratch (device globals; allocation-free contract) --------
__device__ int            g_deg[NND];
__device__ float          g_dinv[NND];
__device__ float          g_h[(size_t)NND * HDIM];
__device__ float          g_agg[(size_t)NND * HDIM];
__device__ float          g_feat[(size_t)NND * HDIM];
__device__ __nv_bfloat16  g_ah[(size_t)NND * 256];
__device__ __nv_bfloat16  g_al[(size_t)NND * 256];
__device__ __nv_bfloat16  g_wh[128 * 256];
__device__ __nv_bfloat16  g_wl[128 * 256];

// ---------------- degree / norm ----------------
__global__ void deg_init_kernel(int n) {
    int i = blockIdx.x * blockDim.x + threadIdx.x;
    if (i < n) g_deg[i] = 1;  // self-loop
}
__global__ void deg_count_kernel(const int* __restrict__ dst, int E) {
    for (int e = blockIdx.x * blockDim.x + threadIdx.x; e < E;
         e += gridDim.x * blockDim.x)
        atomicAdd(&g_deg[dst[e]], 1);
}
__global__ void dinv_kernel(int n) {
    int i = blockIdx.x * blockDim.x + threadIdx.x;
    if (i < n) g_dinv[i] = rsqrtf((float)g_deg[i]);
}

// ---------------- bf16 split helpers ----------------
__device__ __forceinline__ void split_store4(float4 v, __nv_bfloat16* ah,
                                             __nv_bfloat16* al, size_t off) {
    float hx = __bfloat162float(__float2bfloat16(v.x));
    float hy = __bfloat162float(__float2bfloat16(v.y));
    float hz = __bfloat162float(__float2bfloat16(v.z));
    float hw = __bfloat162float(__float2bfloat16(v.w));
    __nv_bfloat162 h01 = __floats2bfloat162_rn(hx, hy);
    __nv_bfloat162 h23 = __floats2bfloat162_rn(hz, hw);
    __nv_bfloat162 l01 = __floats2bfloat162_rn(v.x - hx, v.y - hy);
    __nv_bfloat162 l23 = __floats2bfloat162_rn(v.z - hz, v.w - hw);
    uint2 hp, lp;
    hp.x = *(uint32_t*)&h01; hp.y = *(uint32_t*)&h23;
    lp.x = *(uint32_t*)&l01; lp.y = *(uint32_t*)&l23;
    *(uint2*)&ah[off] = hp;
    *(uint2*)&al[off] = lp;
}

// x [N,256] f32 -> g_ah/g_al bf16 (ld 256)
__global__ void convert_x_kernel(const float* __restrict__ x, int total4) {
    int i = blockIdx.x * blockDim.x + threadIdx.x;
    if (i >= total4) return;
    float4 v = ((const float4*)x)[i];
    split_store4(v, g_ah, g_al, (size_t)i * 4);
}

// W [K,128] f32 -> g_wh/g_wl transposed [128,K] bf16
__global__ void convert_w_kernel(const float* __restrict__ W, int K) {
    int i = blockIdx.x * blockDim.x + threadIdx.x;
    if (i >= 128 * K) return;
    int n = i / K, k = i % K;
    float v = W[k * 128 + n];
    float h = __bfloat162float(__float2bfloat16(v));
    g_wh[n * K + k] = __float2bfloat16(h);
    g_wl[n * K + k] = __float2bfloat16(v - h);
}

// ---------------- HMMA GEMM: D = A @ W^T (bf16x3 split), row-scaled by dinv --
// A (hi/lo): [M,K] bf16 row-major. W (hi/lo): [128,K] bf16 ("col" operand).
// mma.sync.aligned.m16n8k16.row.col.f32.bf16.bf16.f32
#define MMA16816(d, a, b) \
    asm volatile( \
        "mma.sync.aligned.m16n8k16.row.col.f32.bf16.bf16.f32 " \
        "{%0,%1,%2,%3}, {%4,%5,%6,%7}, {%8,%9}, {%0,%1,%2,%3};" \
        : "+f"((d)[0]), "+f"((d)[1]), "+f"((d)[2]), "+f"((d)[3]) \
        : "r"((a)[0]), "r"((a)[1]), "r"((a)[2]), "r"((a)[3]), \
          "r"((b)[0]), "r"((b)[1]))

template <int K>
__global__ __launch_bounds__(256, 1) void gemm_mma_kernel(
    const __nv_bfloat16* __restrict__ Ah, const __nv_bfloat16* __restrict__ Al,
    float* __restrict__ H, float* __restrict__ AGG,
    const float* __restrict__ dinv, int M)
{
    extern __shared__ char smem[];
    const int PW = K + 8;   // W row pitch (bf16): conflict-free + 16B aligned
    const int PA = 24;      // A row pitch (bf16)

    __nv_bfloat16* sWh = (__nv_bfloat16*)smem;
    __nv_bfloat16* sWl = sWh + 128 * PW;
    __nv_bfloat16* sA  = sWl + 128 * PW;   // [stage][buf][128][PA]

    const int tid = threadIdx.x, lane = tid & 31, wid = tid >> 5;
    const int wm = wid & 3, wn = wid >> 2;     // warp tile: 32 rows x 64 cols
    const int m0 = blockIdx.x * 128;

    // ---- copy W (hi+lo) into SMEM (uint4 chunks) ----
    const int WCH = 128 * (K / 8);
    for (int i = tid; i < WCH; i += 256) {
        int n = i / (K / 8), c = i % (K / 8);
        *(uint4*)(sWh + n * PW + c * 8) = *(const uint4*)(g_wh + n * K + c * 8);
        *(uint4*)(sWl + n * PW + c * 8) = *(const uint4*)(g_wl + n * K + c * 8);
    }

    // ---- A k-slice copy: 128 rows x 16 bf16, hi+lo ----
    auto copyA = [&](int ks, int st) {
        int buf = tid >> 7, row = tid & 127;
        int gr = m0 + row;
        const __nv_bfloat16* src = buf ? Al : Ah;
        uint4 v0 = make_uint4(0u, 0u, 0u, 0u), v1 = v0;
        if (gr < M) {
            const uint4* p = (const uint4*)(src + (size_t)gr * K + ks * 16);
            v0 = p[0]; v1 = p[1];
        }
        __nv_bfloat16* d = sA + ((st * 2 + buf) * 128 + row) * PA;
        *(uint4*)d = v0; *(uint4*)(d + 8) = v1;
    };

    float acc[2][8][4];
#pragma unroll
    for (int mt = 0; mt < 2; mt++)
#pragma unroll
        for (int nt = 0; nt < 8; nt++)
#pragma unroll
            for (int j = 0; j < 4; j++) acc[mt][nt][j] = 0.f;

    const int NS = K / 16;
    copyA(0, 0);
    __syncthreads();

    const int ar0 = wm * 32 + (lane >> 2);
    const int kk  = (lane & 3) * 2;
    const int nb  = wn * 64 + (lane >> 2);

    for (int ks = 0; ks < NS; ks++) {
        int st = ks & 1;
        if (ks + 1 < NS) copyA(ks + 1, st ^ 1);

        const __nv_bfloat16* Abh = sA + (st * 2 + 0) * 128 * PA;
        const __nv_bfloat16* Abl = sA + (st * 2 + 1) * 128 * PA;

        uint32_t ah[2][4], al[2][4];
#pragma unroll
        for (int mt = 0; mt < 2; mt++) {
            int r = ar0 + mt * 16;
            ah[mt][0] = *(const uint32_t*)(Abh + r * PA + kk);
            ah[mt][1] = *(const uint32_t*)(Abh + (r + 8) * PA + kk);
            ah[mt][2] = *(const uint32_t*)(Abh + r * PA + kk + 8);
            ah[mt][3] = *(const uint32_t*)(Abh + (r + 8) * PA + kk + 8);
            al[mt][0] = *(const uint32_t*)(Abl + r * PA + kk);
            al[mt][1] = *(const uint32_t*)(Abl + (r + 8) * PA + kk);
            al[mt][2] = *(const uint32_t*)(Abl + r * PA + kk + 8);
            al[mt][3] = *(const uint32_t*)(Abl + (r + 8) * PA + kk + 8);
        }
        uint32_t bh[8][2], bl[8][2];
        int kw = ks * 16 + kk;
#pragma unroll
        for (int nt = 0; nt < 8; nt++) {
            const __nv_bfloat16* ph = sWh + (nb + nt * 8) * PW + kw;
            const __nv_bfloat16* pl = sWl + (nb + nt * 8) * PW + kw;
            bh[nt][0] = *(const uint32_t*)ph;
            bh[nt][1] = *(const uint32_t*)(ph + 8);
            bl[nt][0] = *(const uint32_t*)pl;
            bl[nt][1] = *(const uint32_t*)(pl + 8);
        }
#pragma unroll
        for (int mt = 0; mt < 2; mt++)
#pragma unroll
            for (int nt = 0; nt < 8; nt++) {
                MMA16816(acc[mt][nt], ah[mt], bh[nt]);  // hi*hi
                MMA16816(acc[mt][nt], ah[mt], bl[nt]);  // hi*lo
                MMA16816(acc[mt][nt], al[mt], bh[nt]);  // lo*hi
            }
        __syncthreads();
    }

    // ---- epilogue: scale rows by dinv, write H and AGG ----
    const int cbase = wn * 64 + (lane & 3) * 2;
#pragma unroll
    for (int mt = 0; mt < 2; mt++) {
        int ra = m0 + wm * 32 + mt * 16 + (lane >> 2);
        int rb = ra + 8;
        float sa = (ra < M) ? dinv[ra] : 0.f;
        float sb = (rb < M) ? dinv[rb] : 0.f;
#pragma unroll
        for (int nt = 0; nt < 8; nt++) {
            int col = cbase + nt * 8;
            if (ra < M) {
                float2 v = make_float2(acc[mt][nt][0] * sa, acc[mt][nt][1] * sa);
                *(float2*)&H[(size_t)ra * HDIM + col]   = v;
                *(float2*)&AGG[(size_t)ra * HDIM + col] = v;
            }
            if (rb < M) {
                float2 v = make_float2(acc[mt][nt][2] * sb, acc[mt][nt][3] * sb);
                *(float2*)&H[(size_t)rb * HDIM + col]   = v;
                *(float2*)&AGG[(size_t)rb * HDIM + col] = v;
            }
        }
    }
}

// ---------------- edge scatter: AGG[dst] += H[src], 1 warp/edge --------------
__global__ __launch_bounds__(256) void scatter_kernel(
    const float* __restrict__ H, float* __restrict__ AGG,
    const int* __restrict__ src, const int* __restrict__ dst, int E)
{
    int gw   = (blockIdx.x * blockDim.x + threadIdx.x) >> 5;
    int lane = threadIdx.x & 31;
    if (gw >= E) return;
    int s = src[gw], d = dst[gw];
    float4 v = *(const float4*)&H[(size_t)s * HDIM + lane * 4];
    float* p = &AGG[(size_t)d * HDIM + lane * 4];
    asm volatile("red.global.add.v4.f32 [%0], {%1,%2,%3,%4};" ::
                 "l"(p), "f"(v.x), "f"(v.y), "f"(v.z), "f"(v.w) : "memory");
}

// ---------------- finalize (layers 0,1): relu(AGG*dinv+b) -> bf16 hi/lo ------
__global__ __launch_bounds__(256) void finalize_bf16_kernel(
    const float* __restrict__ AGG, const float* __restrict__ bias, int M)
{
    int idx = blockIdx.x * blockDim.x + threadIdx.x;
    if (idx >= M * 32) return;
    int row = idx >> 5;
    int c4  = (idx & 31) * 4;
    float s = g_dinv[row];
    float4 v  = *(const float4*)&AGG[(size_t)row * HDIM + c4];
    float4 bb = *(const float4*)&bias[c4];
    v.x = fmaxf(v.x * s + bb.x, 0.f); v.y = fmaxf(v.y * s + bb.y, 0.f);
    v.z = fmaxf(v.z * s + bb.z, 0.f); v.w = fmaxf(v.w * s + bb.w, 0.f);
    split_store4(v, g_ah, g_al, (size_t)row * HDIM + c4);
}

// ---------------- finalize (layer 2): AGG*dinv+b -> fp32 ---------------------
__global__ __launch_bounds__(256) void finalize_f32_kernel(
    const float* __restrict__ AGG, const float* __restrict__ bias,
    float* __restrict__ OUT, int M)
{
    int idx = blockIdx.x * blockDim.x + threadIdx.x;
    if (idx >= M * 32) return;
    int row = idx >> 5;
    int c4  = (idx & 31) * 4;
    float s = g_dinv[row];
    float4 v  = *(const float4*)&AGG[(size_t)row * HDIM + c4];
    float4 bb = *(const float4*)&bias[c4];
    v.x = v.x * s + bb.x; v.y = v.y * s + bb.y;
    v.z = v.z * s + bb.z; v.w = v.w * s + bb.w;
    *(float4*)&OUT[(size_t)row * HDIM + c4] = v;
}

// ---------------- decode: logits[e] = dot(Z[a], Z[b]), 1 warp/edge -----------
__global__ __launch_bounds__(256) void decode_kernel(
    const float* __restrict__ Z, const int* __restrict__ ea,
    const int* __restrict__ eb, float* __restrict__ out, int EL)
{
    int gw   = (blockIdx.x * blockDim.x + threadIdx.x) >> 5;
    int lane = threadIdx.x & 31;
    if (gw >= EL) return;
    int i = ea[gw], j = eb[gw];
    float4 u = *(const float4*)&Z[(size_t)i * HDIM + lane * 4];
    float4 v = *(const float4*)&Z[(size_t)j * HDIM + lane * 4];
    float p = u.x * v.x + u.y * v.y + u.z * v.z + u.w * v.w;
#pragma unroll
    for (int o = 16; o; o >>= 1) p += __shfl_xor_sync(0xffffffffu, p, o);
    if (lane == 0) out[gw] = p;
}

extern "C" void kernel_launch(void* const* d_in, const int* in_sizes, int n_in,
                              void* d_out, int out_size)
{
    const float* x   = (const float*)d_in[0];
    const int*   ei  = (const int*)d_in[1];
    const int*   eli = (const int*)d_in[2];
    const float* W0  = (const float*)d_in[3];
    const float* b0  = (const float*)d_in[4];
    const float* W1  = (const float*)d_in[5];
    const float* b1  = (const float*)d_in[6];
    const float* W2  = (const float*)d_in[7];
    const float* b2  = (const float*)d_in[8];
    float* logits = (float*)d_out;

    const int N  = in_sizes[0] / 256;   // 50000
    const int E  = in_sizes[1] / 2;     // 320000
    const int EL = in_sizes[2] / 2;     // 200000
    const int* src = ei;
    const int* dst = ei + E;
    const int* la  = eli;
    const int* lb  = eli + EL;

    float *p_h, *p_agg, *p_feat, *p_dinv;
    __nv_bfloat16 *p_ah, *p_al;
    cudaGetSymbolAddress((void**)&p_h,    g_h);
    cudaGetSymbolAddress((void**)&p_agg,  g_agg);
    cudaGetSymbolAddress((void**)&p_feat, g_feat);
    cudaGetSymbolAddress((void**)&p_dinv, g_dinv);
    cudaGetSymbolAddress((void**)&p_ah,   g_ah);
    cudaGetSymbolAddress((void**)&p_al,   g_al);

    // dynamic smem: 2*128*(K+8)*2B (W hi+lo) + 4*128*24*2B (A stages)
    const int SMEM256 = (2 * 128 * 264 + 4 * 128 * 24) * 2;  // 159744
    const int SMEM128 = (2 * 128 * 136 + 4 * 128 * 24) * 2;  //  94208
    cudaFuncSetAttribute(gemm_mma_kernel<256>,
                         cudaFuncAttributeMaxDynamicSharedMemorySize, SMEM256);
    cudaFuncSetAttribute(gemm_mma_kernel<128>,
                         cudaFuncAttributeMaxDynamicSharedMemorySize, SMEM128);

    const int TB = 256;
    deg_init_kernel<<<(N + TB - 1) / TB, TB>>>(N);
    deg_count_kernel<<<512, TB>>>(dst, E);
    dinv_kernel<<<(N + TB - 1) / TB, TB>>>(N);

    const int mtiles      = (N + 127) / 128;
    const int scat_blocks = (E + 7) / 8;
    const int fin_blocks  = (N * 32 + TB - 1) / TB;

    // Layer 0: K=256
    convert_x_kernel<<<(N * 64 + TB - 1) / TB, TB>>>(x, N * 64);
    convert_w_kernel<<<(128 * 256 + TB - 1) / TB, TB>>>(W0, 256);
    gemm_mma_kernel<256><<<mtiles, TB, SMEM256>>>(p_ah, p_al, p_h, p_agg, p_dinv, N);
    scatter_kernel<<<scat_blocks, TB>>>(p_h, p_agg, src, dst, E);
    finalize_bf16_kernel<<<fin_blocks, TB>>>(p_agg, b0, N);

    // Layer 1: K=128
    convert_w_kernel<<<(128 * 128 + TB - 1) / TB, TB>>>(W1, 128);
    gemm_mma_kernel<128><<<mtiles, TB, SMEM128>>>(p_ah, p_al, p_h, p_agg, p_dinv, N);
    scatter_kernel<<<scat_blocks, TB>>>(p_h, p_agg, src, dst, E);
    finalize_bf16_kernel<<<fin_blocks, TB>>>(p_agg, b1, N);

    // Layer 2: K=128, no relu, fp32 out
    convert_w_kernel<<<(128 * 128 + TB - 1) / TB, TB>>>(W2, 128);
    gemm_mma_kernel<128><<<mtiles, TB, SMEM128>>>(p_ah, p_al, p_h, p_agg, p_dinv, N);
    scatter_kernel<<<scat_blocks, TB>>>(p_h, p_agg, src, dst, E);
    finalize_f32_kernel<<<fin_blocks, TB>>>(p_agg, b2, p_feat, N);

    // Decode
    decode_kernel<<<(EL + 7) / 8, TB>>>(p_feat, la, lb, logits, EL);
}

// round 8
// speedup vs baseline: 1.4358x; 1.2505x over previous
#include <cuda_runtime.h>
#include <cuda_bf16.h>
#include <math.h>
#include <stdint.h>

#define NND 50000
#define EMAX 320000
#define HDIM 128

// ---------------- scratch (device globals; allocation-free contract) --------
__device__ int            g_deg[NND];
__device__ float          g_dinv[NND];
__device__ float          g_h[(size_t)NND * HDIM];
__device__ float          g_agg[(size_t)NND * HDIM];
__device__ float          g_feat[(size_t)NND * HDIM];
__device__ __nv_bfloat16  g_ah[(size_t)NND * HDIM];
__device__ __nv_bfloat16  g_al[(size_t)NND * HDIM];
__device__ __nv_bfloat16  g_wh[128 * 256];
__device__ __nv_bfloat16  g_wl[128 * 256];
// CSR
__device__ int g_off[NND + 1];
__device__ int g_cur[NND];
__device__ int g_csr[EMAX];
__device__ int g_part[256];

// ---------------- degree / norm ----------------
__global__ void deg_init_kernel(int n) {
    int i = blockIdx.x * blockDim.x + threadIdx.x;
    if (i < n) g_deg[i] = 1;  // self-loop
}
__global__ void deg_count_kernel(const int* __restrict__ dst, int E) {
    for (int e = blockIdx.x * blockDim.x + threadIdx.x; e < E;
         e += gridDim.x * blockDim.x)
        atomicAdd(&g_deg[dst[e]], 1);
}
__global__ void dinv_kernel(int n) {
    int i = blockIdx.x * blockDim.x + threadIdx.x;
    if (i < n) g_dinv[i] = rsqrtf((float)g_deg[i]);
}

// ---------------- CSR build: exclusive scan of indegree + fill ---------------
__global__ void scan_block_kernel(int n) {
    __shared__ int sh[256];
    int i = blockIdx.x * 256 + threadIdx.x;
    int v = (i < n) ? g_deg[i] - 1 : 0;
    sh[threadIdx.x] = v;
    __syncthreads();
#pragma unroll
    for (int o = 1; o < 256; o <<= 1) {
        int t = (threadIdx.x >= o) ? sh[threadIdx.x - o] : 0;
        __syncthreads();
        sh[threadIdx.x] += t;
        __syncthreads();
    }
    int incl = sh[threadIdx.x];
    if (i < n) g_off[i] = incl - v;                 // block-local exclusive
    if (threadIdx.x == 255) g_part[blockIdx.x] = incl;
}
__global__ void scan_part_kernel(int nb) {
    __shared__ int sh[256];
    int t = threadIdx.x;
    int v = (t < nb) ? g_part[t] : 0;
    sh[t] = v;
    __syncthreads();
#pragma unroll
    for (int o = 1; o < 256; o <<= 1) {
        int u = (t >= o) ? sh[t - o] : 0;
        __syncthreads();
        sh[t] += u;
        __syncthreads();
    }
    g_part[t] = sh[t] - v;                          // exclusive block offsets
}
__global__ void scan_add_kernel(int n, int E) {
    int i = blockIdx.x * 256 + threadIdx.x;
    if (i < n) {
        int o = g_off[i] + g_part[blockIdx.x];
        g_off[i] = o;
        g_cur[i] = o;
    }
    if (i == 0) g_off[n] = E;
}
__global__ void csr_fill_kernel(const int* __restrict__ src,
                                const int* __restrict__ dst, int E) {
    for (int e = blockIdx.x * blockDim.x + threadIdx.x; e < E;
         e += gridDim.x * blockDim.x) {
        int p = atomicAdd(&g_cur[dst[e]], 1);
        g_csr[p] = src[e];
    }
}

// ---------------- bf16 split helpers ----------------
__device__ __forceinline__ void split_store4(float4 v, __nv_bfloat16* ah,
                                             __nv_bfloat16* al, size_t off) {
    float hx = __bfloat162float(__float2bfloat16(v.x));
    float hy = __bfloat162float(__float2bfloat16(v.y));
    float hz = __bfloat162float(__float2bfloat16(v.z));
    float hw = __bfloat162float(__float2bfloat16(v.w));
    __nv_bfloat162 h01 = __floats2bfloat162_rn(hx, hy);
    __nv_bfloat162 h23 = __floats2bfloat162_rn(hz, hw);
    __nv_bfloat162 l01 = __floats2bfloat162_rn(v.x - hx, v.y - hy);
    __nv_bfloat162 l23 = __floats2bfloat162_rn(v.z - hz, v.w - hw);
    uint2 hp, lp;
    hp.x = *(uint32_t*)&h01; hp.y = *(uint32_t*)&h23;
    lp.x = *(uint32_t*)&l01; lp.y = *(uint32_t*)&l23;
    *(uint2*)&ah[off] = hp;
    *(uint2*)&al[off] = lp;
}

// W [K,128] f32 -> g_wh/g_wl transposed [128,K] bf16
__global__ void convert_w_kernel(const float* __restrict__ W, int K) {
    int i = blockIdx.x * blockDim.x + threadIdx.x;
    if (i >= 128 * K) return;
    int n = i / K, k = i % K;
    float v = W[k * 128 + n];
    float h = __bfloat162float(__float2bfloat16(v));
    g_wh[n * K + k] = __float2bfloat16(h);
    g_wl[n * K + k] = __float2bfloat16(v - h);
}

// ---------------- HMMA GEMM: D = A @ W^T (bf16x3 split), row-scaled by dinv --
#define MMA16816(d, a, b) \
    asm volatile( \
        "mma.sync.aligned.m16n8k16.row.col.f32.bf16.bf16.f32 " \
        "{%0,%1,%2,%3}, {%4,%5,%6,%7}, {%8,%9}, {%0,%1,%2,%3};" \
        : "+f"((d)[0]), "+f"((d)[1]), "+f"((d)[2]), "+f"((d)[3]) \
        : "r"((a)[0]), "r"((a)[1]), "r"((a)[2]), "r"((a)[3]), \
          "r"((b)[0]), "r"((b)[1]))

// FUSE=true: A comes from fp32 Xf (split to hi/lo in registers during copy).
// FUSE=false: A comes from pre-split bf16 Ah/Al.
template <int K, bool FUSE>
__global__ __launch_bounds__(256, 1) void gemm_mma_kernel(
    const __nv_bfloat16* __restrict__ Ah, const __nv_bfloat16* __restrict__ Al,
    const float* __restrict__ Xf,
    float* __restrict__ H, float* __restrict__ AGG,
    const float* __restrict__ dinv, int M)
{
    extern __shared__ char smem[];
    const int PW = K + 8;   // W row pitch (bf16)
    const int PA = 24;      // A row pitch (bf16)

    __nv_bfloat16* sWh = (__nv_bfloat16*)smem;
    __nv_bfloat16* sWl = sWh + 128 * PW;
    __nv_bfloat16* sA  = sWl + 128 * PW;   // [stage][buf][128][PA]

    const int tid = threadIdx.x, lane = tid & 31, wid = tid >> 5;
    const int wm = wid & 3, wn = wid >> 2;     // warp tile: 32 rows x 64 cols
    const int m0 = blockIdx.x * 128;

    // ---- copy W (hi+lo) into SMEM ----
    const int WCH = 128 * (K / 8);
    for (int i = tid; i < WCH; i += 256) {
        int n = i / (K / 8), c = i % (K / 8);
        *(uint4*)(sWh + n * PW + c * 8) = *(const uint4*)(g_wh + n * K + c * 8);
        *(uint4*)(sWl + n * PW + c * 8) = *(const uint4*)(g_wl + n * K + c * 8);
    }

    // ---- A k-slice copy: 128 rows x 16 bf16, hi+lo ----
    auto copyA = [&](int ks, int st) {
        if (FUSE) {
            int row = tid >> 1, half = tid & 1;
            int gr = m0 + row;
            float4 v0 = make_float4(0.f, 0.f, 0.f, 0.f), v1 = v0;
            if (gr < M) {
                const float4* p = (const float4*)(Xf + (size_t)gr * K + ks * 16 + half * 8);
                v0 = p[0]; v1 = p[1];
            }
            float f[8] = {v0.x, v0.y, v0.z, v0.w, v1.x, v1.y, v1.z, v1.w};
            uint32_t hi[4], lo[4];
#pragma unroll
            for (int j = 0; j < 4; j++) {
                float a = f[2 * j], b = f[2 * j + 1];
                float ha = __bfloat162float(__float2bfloat16(a));
                float hb = __bfloat162float(__float2bfloat16(b));
                __nv_bfloat162 hh = __floats2bfloat162_rn(ha, hb);
                __nv_bfloat162 ll = __floats2bfloat162_rn(a - ha, b - hb);
                hi[j] = *(uint32_t*)&hh;
                lo[j] = *(uint32_t*)&ll;
            }
            __nv_bfloat16* dh = sA + ((st * 2 + 0) * 128 + row) * PA + half * 8;
            __nv_bfloat16* dl = sA + ((st * 2 + 1) * 128 + row) * PA + half * 8;
            *(uint4*)dh = make_uint4(hi[0], hi[1], hi[2], hi[3]);
            *(uint4*)dl = make_uint4(lo[0], lo[1], lo[2], lo[3]);
        } else {
            int buf = tid >> 7, row = tid & 127;
            int gr = m0 + row;
            const __nv_bfloat16* src = buf ? Al : Ah;
            uint4 v0 = make_uint4(0u, 0u, 0u, 0u), v1 = v0;
            if (gr < M) {
                const uint4* p = (const uint4*)(src + (size_t)gr * K + ks * 16);
                v0 = p[0]; v1 = p[1];
            }
            __nv_bfloat16* d = sA + ((st * 2 + buf) * 128 + row) * PA;
            *(uint4*)d = v0; *(uint4*)(d + 8) = v1;
        }
    };

    float acc[2][8][4];
#pragma unroll
    for (int mt = 0; mt < 2; mt++)
#pragma unroll
        for (int nt = 0; nt < 8; nt++)
#pragma unroll
            for (int j = 0; j < 4; j++) acc[mt][nt][j] = 0.f;

    const int NS = K / 16;
    copyA(0, 0);
    __syncthreads();

    const int ar0 = wm * 32 + (lane >> 2);
    const int kk  = (lane & 3) * 2;
    const int nb  = wn * 64 + (lane >> 2);

    for (int ks = 0; ks < NS; ks++) {
        int st = ks & 1;
        if (ks + 1 < NS) copyA(ks + 1, st ^ 1);

        const __nv_bfloat16* Abh = sA + (st * 2 + 0) * 128 * PA;
        const __nv_bfloat16* Abl = sA + (st * 2 + 1) * 128 * PA;

        uint32_t ah[2][4], al[2][4];
#pragma unroll
        for (int mt = 0; mt < 2; mt++) {
            int r = ar0 + mt * 16;
            ah[mt][0] = *(const uint32_t*)(Abh + r * PA + kk);
            ah[mt][1] = *(const uint32_t*)(Abh + (r + 8) * PA + kk);
            ah[mt][2] = *(const uint32_t*)(Abh + r * PA + kk + 8);
            ah[mt][3] = *(const uint32_t*)(Abh + (r + 8) * PA + kk + 8);
            al[mt][0] = *(const uint32_t*)(Abl + r * PA + kk);
            al[mt][1] = *(const uint32_t*)(Abl + (r + 8) * PA + kk);
            al[mt][2] = *(const uint32_t*)(Abl + r * PA + kk + 8);
            al[mt][3] = *(const uint32_t*)(Abl + (r + 8) * PA + kk + 8);
        }
        uint32_t bh[8][2], bl[8][2];
        int kw = ks * 16 + kk;
#pragma unroll
        for (int nt = 0; nt < 8; nt++) {
            const __nv_bfloat16* ph = sWh + (nb + nt * 8) * PW + kw;
            const __nv_bfloat16* pl = sWl + (nb + nt * 8) * PW + kw;
            bh[nt][0] = *(const uint32_t*)ph;
            bh[nt][1] = *(const uint32_t*)(ph + 8);
            bl[nt][0] = *(const uint32_t*)pl;
            bl[nt][1] = *(const uint32_t*)(pl + 8);
        }
#pragma unroll
        for (int mt = 0; mt < 2; mt++)
#pragma unroll
            for (int nt = 0; nt < 8; nt++) {
                MMA16816(acc[mt][nt], ah[mt], bh[nt]);  // hi*hi
                MMA16816(acc[mt][nt], ah[mt], bl[nt]);  // hi*lo
                MMA16816(acc[mt][nt], al[mt], bh[nt]);  // lo*hi
            }
        __syncthreads();
    }

    // ---- epilogue: scale rows by dinv, write H and AGG ----
    const int cbase = wn * 64 + (lane & 3) * 2;
#pragma unroll
    for (int mt = 0; mt < 2; mt++) {
        int ra = m0 + wm * 32 + mt * 16 + (lane >> 2);
        int rb = ra + 8;
        float sa = (ra < M) ? dinv[ra] : 0.f;
        float sb = (rb < M) ? dinv[rb] : 0.f;
#pragma unroll
        for (int nt = 0; nt < 8; nt++) {
            int col = cbase + nt * 8;
            if (ra < M) {
                float2 v = make_float2(acc[mt][nt][0] * sa, acc[mt][nt][1] * sa);
                *(float2*)&H[(size_t)ra * HDIM + col]   = v;
                *(float2*)&AGG[(size_t)ra * HDIM + col] = v;
            }
            if (rb < M) {
                float2 v = make_float2(acc[mt][nt][2] * sb, acc[mt][nt][3] * sb);
                *(float2*)&H[(size_t)rb * HDIM + col]   = v;
                *(float2*)&AGG[(size_t)rb * HDIM + col] = v;
            }
        }
    }
}

// ---------------- CSR aggregation: AGG[n] += sum_{s in nbr(n)} H[s] ----------
__global__ __launch_bounds__(256) void agg_csr_kernel(
    const float* __restrict__ H, float* __restrict__ AGG, int N)
{
    int gw   = (blockIdx.x * blockDim.x + threadIdx.x) >> 5;
    int lane = threadIdx.x & 31;
    if (gw >= N) return;
    int s0 = g_off[gw], s1 = g_off[gw + 1];
    if (s0 == s1) return;                      // self term already in AGG
    float4 acc = *(const float4*)&AGG[(size_t)gw * HDIM + lane * 4];
    for (int j = s0; j < s1; j++) {
        int s = g_csr[j];
        float4 v = __ldg((const float4*)&H[(size_t)s * HDIM + lane * 4]);
        acc.x += v.x; acc.y += v.y; acc.z += v.z; acc.w += v.w;
    }
    *(float4*)&AGG[(size_t)gw * HDIM + lane * 4] = acc;
}

// ---------------- finalize (layers 0,1): relu(AGG*dinv+b) -> bf16 hi/lo ------
__global__ __launch_bounds__(256) void finalize_bf16_kernel(
    const float* __restrict__ AGG, const float* __restrict__ bias, int M)
{
    int idx = blockIdx.x * blockDim.x + threadIdx.x;
    if (idx >= M * 32) return;
    int row = idx >> 5;
    int c4  = (idx & 31) * 4;
    float s = g_dinv[row];
    float4 v  = *(const float4*)&AGG[(size_t)row * HDIM + c4];
    float4 bb = *(const float4*)&bias[c4];
    v.x = fmaxf(v.x * s + bb.x, 0.f); v.y = fmaxf(v.y * s + bb.y, 0.f);
    v.z = fmaxf(v.z * s + bb.z, 0.f); v.w = fmaxf(v.w * s + bb.w, 0.f);
    split_store4(v, g_ah, g_al, (size_t)row * HDIM + c4);
}

// ---------------- finalize (layer 2): AGG*dinv+b -> fp32 ---------------------
__global__ __launch_bounds__(256) void finalize_f32_kernel(
    const float* __restrict__ AGG, const float* __restrict__ bias,
    float* __restrict__ OUT, int M)
{
    int idx = blockIdx.x * blockDim.x + threadIdx.x;
    if (idx >= M * 32) return;
    int row = idx >> 5;
    int c4  = (idx & 31) * 4;
    float s = g_dinv[row];
    float4 v  = *(const float4*)&AGG[(size_t)row * HDIM + c4];
    float4 bb = *(const float4*)&bias[c4];
    v.x = v.x * s + bb.x; v.y = v.y * s + bb.y;
    v.z = v.z * s + bb.z; v.w = v.w * s + bb.w;
    *(float4*)&OUT[(size_t)row * HDIM + c4] = v;
}

// ---------------- decode: logits[e] = dot(Z[a], Z[b]), 1 warp/edge -----------
__global__ __launch_bounds__(256) void decode_kernel(
    const float* __restrict__ Z, const int* __restrict__ ea,
    const int* __restrict__ eb, float* __restrict__ out, int EL)
{
    int gw   = (blockIdx.x * blockDim.x + threadIdx.x) >> 5;
    int lane = threadIdx.x & 31;
    if (gw >= EL) return;
    int i = ea[gw], j = eb[gw];
    float4 u = *(const float4*)&Z[(size_t)i * HDIM + lane * 4];
    float4 v = *(const float4*)&Z[(size_t)j * HDIM + lane * 4];
    float p = u.x * v.x + u.y * v.y + u.z * v.z + u.w * v.w;
#pragma unroll
    for (int o = 16; o; o >>= 1) p += __shfl_xor_sync(0xffffffffu, p, o);
    if (lane == 0) out[gw] = p;
}

extern "C" void kernel_launch(void* const* d_in, const int* in_sizes, int n_in,
                              void* d_out, int out_size)
{
    const float* x   = (const float*)d_in[0];
    const int*   ei  = (const int*)d_in[1];
    const int*   eli = (const int*)d_in[2];
    const float* W0  = (const float*)d_in[3];
    const float* b0  = (const float*)d_in[4];
    const float* W1  = (const float*)d_in[5];
    const float* b1  = (const float*)d_in[6];
    const float* W2  = (const float*)d_in[7];
    const float* b2  = (const float*)d_in[8];
    float* logits = (float*)d_out;

    const int N  = in_sizes[0] / 256;   // 50000
    const int E  = in_sizes[1] / 2;     // 320000
    const int EL = in_sizes[2] / 2;     // 200000
    const int* src = ei;
    const int* dst = ei + E;
    const int* la  = eli;
    const int* lb  = eli + EL;

    float *p_h, *p_agg, *p_feat, *p_dinv;
    __nv_bfloat16 *p_ah, *p_al;
    cudaGetSymbolAddress((void**)&p_h,    g_h);
    cudaGetSymbolAddress((void**)&p_agg,  g_agg);
    cudaGetSymbolAddress((void**)&p_feat, g_feat);
    cudaGetSymbolAddress((void**)&p_dinv, g_dinv);
    cudaGetSymbolAddress((void**)&p_ah,   g_ah);
    cudaGetSymbolAddress((void**)&p_al,   g_al);

    const int SMEM256 = (2 * 128 * 264 + 4 * 128 * 24) * 2;  // 159744
    const int SMEM128 = (2 * 128 * 136 + 4 * 128 * 24) * 2;  //  94208
    cudaFuncSetAttribute((gemm_mma_kernel<256, true>),
                         cudaFuncAttributeMaxDynamicSharedMemorySize, SMEM256);
    cudaFuncSetAttribute((gemm_mma_kernel<128, false>),
                         cudaFuncAttributeMaxDynamicSharedMemorySize, SMEM128);

    const int TB = 256;
    const int nscan = (N + 255) / 256;              // 196 blocks

    // degrees + normalization + CSR build
    deg_init_kernel<<<(N + TB - 1) / TB, TB>>>(N);
    deg_count_kernel<<<512, TB>>>(dst, E);
    dinv_kernel<<<(N + TB - 1) / TB, TB>>>(N);
    scan_block_kernel<<<nscan, 256>>>(N);
    scan_part_kernel<<<1, 256>>>(nscan);
    scan_add_kernel<<<nscan, 256>>>(N, E);
    csr_fill_kernel<<<512, TB>>>(src, dst, E);

    const int mtiles     = (N + 127) / 128;
    const int agg_blocks = (N + 7) / 8;             // 8 warps/block
    const int fin_blocks = (N * 32 + TB - 1) / TB;

    // Layer 0: K=256, fused fp32->bf16x2 split of x
    convert_w_kernel<<<(128 * 256 + TB - 1) / TB, TB>>>(W0, 256);
    gemm_mma_kernel<256, true><<<mtiles, TB, SMEM256>>>(
        nullptr, nullptr, x, p_h, p_agg, p_dinv, N);
    agg_csr_kernel<<<agg_blocks, TB>>>(p_h, p_agg, N);
    finalize_bf16_kernel<<<fin_blocks, TB>>>(p_agg, b0, N);

    // Layer 1: K=128
    convert_w_kernel<<<(128 * 128 + TB - 1) / TB, TB>>>(W1, 128);
    gemm_mma_kernel<128, false><<<mtiles, TB, SMEM128>>>(
        p_ah, p_al, nullptr, p_h, p_agg, p_dinv, N);
    agg_csr_kernel<<<agg_blocks, TB>>>(p_h, p_agg, N);
    finalize_bf16_kernel<<<fin_blocks, TB>>>(p_agg, b1, N);

    // Layer 2: K=128, no relu, fp32 out
    convert_w_kernel<<<(128 * 128 + TB - 1) / TB, TB>>>(W2, 128);
    gemm_mma_kernel<128, false><<<mtiles, TB, SMEM128>>>(
        p_ah, p_al, nullptr, p_h, p_agg, p_dinv, N);
    agg_csr_kernel<<<agg_blocks, TB>>>(p_h, p_agg, N);
    finalize_f32_kernel<<<fin_blocks, TB>>>(p_agg, b2, p_feat, N);

    // Decode
    decode_kernel<<<(EL + 7) / 8, TB>>>(p_feat, la, lb, logits, EL);
}

// round 9
// speedup vs baseline: 1.6330x; 1.1373x over previous
#include <cuda_runtime.h>
#include <cuda_bf16.h>
#include <math.h>
#include <stdint.h>

#define NND 50000
#define EMAX 320000
#define HDIM 128

// ---------------- scratch (device globals; allocation-free contract) --------
__device__ int            g_deg[NND];
__device__ float          g_dinv[NND];
__device__ float          g_h[(size_t)NND * HDIM];
__device__ float          g_feat[(size_t)NND * HDIM];
__device__ __nv_bfloat16  g_ah[(size_t)NND * HDIM];
__device__ __nv_bfloat16  g_al[(size_t)NND * HDIM];
__device__ __nv_bfloat16  g_wh[128 * 256];
__device__ __nv_bfloat16  g_wl[128 * 256];
// CSR
__device__ int g_off[NND + 1];
__device__ int g_cur[NND];
__device__ int g_csr[EMAX];
__device__ int g_part[256];

// ---------------- degree ----------------
__global__ void deg_init_kernel(int n) {
    int i = blockIdx.x * blockDim.x + threadIdx.x;
    if (i < n) g_deg[i] = 1;  // self-loop
}
__global__ void deg_count_kernel(const int* __restrict__ dst, int E) {
    for (int e = blockIdx.x * blockDim.x + threadIdx.x; e < E;
         e += gridDim.x * blockDim.x)
        atomicAdd(&g_deg[dst[e]], 1);
}

// ---------------- CSR build: exclusive scan of indegree + fill ---------------
__global__ void scan_block_kernel(int n) {
    __shared__ int sh[256];
    int i = blockIdx.x * 256 + threadIdx.x;
    int v = (i < n) ? g_deg[i] - 1 : 0;
    sh[threadIdx.x] = v;
    __syncthreads();
#pragma unroll
    for (int o = 1; o < 256; o <<= 1) {
        int t = (threadIdx.x >= o) ? sh[threadIdx.x - o] : 0;
        __syncthreads();
        sh[threadIdx.x] += t;
        __syncthreads();
    }
    int incl = sh[threadIdx.x];
    if (i < n) g_off[i] = incl - v;                 // block-local exclusive
    if (threadIdx.x == 255) g_part[blockIdx.x] = incl;
}
__global__ void scan_part_kernel(int nb) {
    __shared__ int sh[256];
    int t = threadIdx.x;
    int v = (t < nb) ? g_part[t] : 0;
    sh[t] = v;
    __syncthreads();
#pragma unroll
    for (int o = 1; o < 256; o <<= 1) {
        int u = (t >= o) ? sh[t - o] : 0;
        __syncthreads();
        sh[t] += u;
        __syncthreads();
    }
    g_part[t] = sh[t] - v;                          // exclusive block offsets
}
// also computes dinv (fused)
__global__ void scan_add_kernel(int n, int E) {
    int i = blockIdx.x * 256 + threadIdx.x;
    if (i < n) {
        int o = g_off[i] + g_part[blockIdx.x];
        g_off[i] = o;
        g_cur[i] = o;
        g_dinv[i] = rsqrtf((float)g_deg[i]);
    }
    if (i == 0) g_off[n] = E;
}
__global__ void csr_fill_kernel(const int* __restrict__ src,
                                const int* __restrict__ dst, int E) {
    for (int e = blockIdx.x * blockDim.x + threadIdx.x; e < E;
         e += gridDim.x * blockDim.x) {
        int p = atomicAdd(&g_cur[dst[e]], 1);
        g_csr[p] = src[e];
    }
}

// ---------------- bf16 split helpers ----------------
__device__ __forceinline__ void split_store4(float4 v, __nv_bfloat16* ah,
                                             __nv_bfloat16* al, size_t off) {
    float hx = __bfloat162float(__float2bfloat16(v.x));
    float hy = __bfloat162float(__float2bfloat16(v.y));
    float hz = __bfloat162float(__float2bfloat16(v.z));
    float hw = __bfloat162float(__float2bfloat16(v.w));
    __nv_bfloat162 h01 = __floats2bfloat162_rn(hx, hy);
    __nv_bfloat162 h23 = __floats2bfloat162_rn(hz, hw);
    __nv_bfloat162 l01 = __floats2bfloat162_rn(v.x - hx, v.y - hy);
    __nv_bfloat162 l23 = __floats2bfloat162_rn(v.z - hz, v.w - hw);
    uint2 hp, lp;
    hp.x = *(uint32_t*)&h01; hp.y = *(uint32_t*)&h23;
    lp.x = *(uint32_t*)&l01; lp.y = *(uint32_t*)&l23;
    *(uint2*)&ah[off] = hp;
    *(uint2*)&al[off] = lp;
}

// W [K,128] f32 -> g_wh/g_wl transposed [128,K] bf16
__global__ void convert_w_kernel(const float* __restrict__ W, int K) {
    int i = blockIdx.x * blockDim.x + threadIdx.x;
    if (i >= 128 * K) return;
    int n = i / K, k = i % K;
    float v = W[k * 128 + n];
    float h = __bfloat162float(__float2bfloat16(v));
    g_wh[n * K + k] = __float2bfloat16(h);
    g_wl[n * K + k] = __float2bfloat16(v - h);
}

// ---------------- HMMA GEMM: H = (A @ W^T) * dinv[row]  (bf16x3 split) -------
#define MMA16816(d, a, b) \
    asm volatile( \
        "mma.sync.aligned.m16n8k16.row.col.f32.bf16.bf16.f32 " \
        "{%0,%1,%2,%3}, {%4,%5,%6,%7}, {%8,%9}, {%0,%1,%2,%3};" \
        : "+f"((d)[0]), "+f"((d)[1]), "+f"((d)[2]), "+f"((d)[3]) \
        : "r"((a)[0]), "r"((a)[1]), "r"((a)[2]), "r"((a)[3]), \
          "r"((b)[0]), "r"((b)[1]))

// FUSE=true: A comes from fp32 Xf (split to hi/lo in registers during copy).
template <int K, bool FUSE>
__global__ __launch_bounds__(256, 1) void gemm_mma_kernel(
    const __nv_bfloat16* __restrict__ Ah, const __nv_bfloat16* __restrict__ Al,
    const float* __restrict__ Xf,
    float* __restrict__ H, const float* __restrict__ dinv, int M)
{
    extern __shared__ char smem[];
    const int PW = K + 8;   // W row pitch (bf16)
    const int PA = 24;      // A row pitch (bf16)

    __nv_bfloat16* sWh = (__nv_bfloat16*)smem;
    __nv_bfloat16* sWl = sWh + 128 * PW;
    __nv_bfloat16* sA  = sWl + 128 * PW;   // [stage][buf][128][PA]

    const int tid = threadIdx.x, lane = tid & 31, wid = tid >> 5;
    const int wm = wid & 3, wn = wid >> 2;     // warp tile: 32 rows x 64 cols
    const int m0 = blockIdx.x * 128;

    const int WCH = 128 * (K / 8);
    for (int i = tid; i < WCH; i += 256) {
        int n = i / (K / 8), c = i % (K / 8);
        *(uint4*)(sWh + n * PW + c * 8) = *(const uint4*)(g_wh + n * K + c * 8);
        *(uint4*)(sWl + n * PW + c * 8) = *(const uint4*)(g_wl + n * K + c * 8);
    }

    auto copyA = [&](int ks, int st) {
        if (FUSE) {
            int row = tid >> 1, half = tid & 1;
            int gr = m0 + row;
            float4 v0 = make_float4(0.f, 0.f, 0.f, 0.f), v1 = v0;
            if (gr < M) {
                const float4* p = (const float4*)(Xf + (size_t)gr * K + ks * 16 + half * 8);
                v0 = p[0]; v1 = p[1];
            }
            float f[8] = {v0.x, v0.y, v0.z, v0.w, v1.x, v1.y, v1.z, v1.w};
            uint32_t hi[4], lo[4];
#pragma unroll
            for (int j = 0; j < 4; j++) {
                float a = f[2 * j], b = f[2 * j + 1];
                float ha = __bfloat162float(__float2bfloat16(a));
                float hb = __bfloat162float(__float2bfloat16(b));
                __nv_bfloat162 hh = __floats2bfloat162_rn(ha, hb);
                __nv_bfloat162 ll = __floats2bfloat162_rn(a - ha, b - hb);
                hi[j] = *(uint32_t*)&hh;
                lo[j] = *(uint32_t*)&ll;
            }
            __nv_bfloat16* dh = sA + ((st * 2 + 0) * 128 + row) * PA + half * 8;
            __nv_bfloat16* dl = sA + ((st * 2 + 1) * 128 + row) * PA + half * 8;
            *(uint4*)dh = make_uint4(hi[0], hi[1], hi[2], hi[3]);
            *(uint4*)dl = make_uint4(lo[0], lo[1], lo[2], lo[3]);
        } else {
            int buf = tid >> 7, row = tid & 127;
            int gr = m0 + row;
            const __nv_bfloat16* src = buf ? Al : Ah;
            uint4 v0 = make_uint4(0u, 0u, 0u, 0u), v1 = v0;
            if (gr < M) {
                const uint4* p = (const uint4*)(src + (size_t)gr * K + ks * 16);
                v0 = p[0]; v1 = p[1];
            }
            __nv_bfloat16* d = sA + ((st * 2 + buf) * 128 + row) * PA;
            *(uint4*)d = v0; *(uint4*)(d + 8) = v1;
        }
    };

    float acc[2][8][4];
#pragma unroll
    for (int mt = 0; mt < 2; mt++)
#pragma unroll
        for (int nt = 0; nt < 8; nt++)
#pragma unroll
            for (int j = 0; j < 4; j++) acc[mt][nt][j] = 0.f;

    const int NS = K / 16;
    copyA(0, 0);
    __syncthreads();

    const int ar0 = wm * 32 + (lane >> 2);
    const int kk  = (lane & 3) * 2;
    const int nb  = wn * 64 + (lane >> 2);

    for (int ks = 0; ks < NS; ks++) {
        int st = ks & 1;
        if (ks + 1 < NS) copyA(ks + 1, st ^ 1);

        const __nv_bfloat16* Abh = sA + (st * 2 + 0) * 128 * PA;
        const __nv_bfloat16* Abl = sA + (st * 2 + 1) * 128 * PA;

        uint32_t ah[2][4], al[2][4];
#pragma unroll
        for (int mt = 0; mt < 2; mt++) {
            int r = ar0 + mt * 16;
            ah[mt][0] = *(const uint32_t*)(Abh + r * PA + kk);
            ah[mt][1] = *(const uint32_t*)(Abh + (r + 8) * PA + kk);
            ah[mt][2] = *(const uint32_t*)(Abh + r * PA + kk + 8);
            ah[mt][3] = *(const uint32_t*)(Abh + (r + 8) * PA + kk + 8);
            al[mt][0] = *(const uint32_t*)(Abl + r * PA + kk);
            al[mt][1] = *(const uint32_t*)(Abl + (r + 8) * PA + kk);
            al[mt][2] = *(const uint32_t*)(Abl + r * PA + kk + 8);
            al[mt][3] = *(const uint32_t*)(Abl + (r + 8) * PA + kk + 8);
        }
        uint32_t bh[8][2], bl[8][2];
        int kw = ks * 16 + kk;
#pragma unroll
        for (int nt = 0; nt < 8; nt++) {
            const __nv_bfloat16* ph = sWh + (nb + nt * 8) * PW + kw;
            const __nv_bfloat16* pl = sWl + (nb + nt * 8) * PW + kw;
            bh[nt][0] = *(const uint32_t*)ph;
            bh[nt][1] = *(const uint32_t*)(ph + 8);
            bl[nt][0] = *(const uint32_t*)pl;
            bl[nt][1] = *(const uint32_t*)(pl + 8);
        }
#pragma unroll
        for (int mt = 0; mt < 2; mt++)
#pragma unroll
            for (int nt = 0; nt < 8; nt++) {
                MMA16816(acc[mt][nt], ah[mt], bh[nt]);  // hi*hi
                MMA16816(acc[mt][nt], ah[mt], bl[nt]);  // hi*lo
                MMA16816(acc[mt][nt], al[mt], bh[nt]);  // lo*hi
            }
        __syncthreads();
    }

    // ---- epilogue: scale rows by dinv, write H only ----
    const int cbase = wn * 64 + (lane & 3) * 2;
#pragma unroll
    for (int mt = 0; mt < 2; mt++) {
        int ra = m0 + wm * 32 + mt * 16 + (lane >> 2);
        int rb = ra + 8;
        float sa = (ra < M) ? dinv[ra] : 0.f;
        float sb = (rb < M) ? dinv[rb] : 0.f;
#pragma unroll
        for (int nt = 0; nt < 8; nt++) {
            int col = cbase + nt * 8;
            if (ra < M)
                *(float2*)&H[(size_t)ra * HDIM + col] =
                    make_float2(acc[mt][nt][0] * sa, acc[mt][nt][1] * sa);
            if (rb < M)
                *(float2*)&H[(size_t)rb * HDIM + col] =
                    make_float2(acc[mt][nt][2] * sb, acc[mt][nt][3] * sb);
        }
    }
}

// ---------------- fused aggregate + finalize ---------------------------------
// acc = H[n] + sum_{s in nbr(n)} H[s];  out = acc*dinv[n] + b;  [relu];
// BF16OUT: split -> g_ah/g_al;  else: f32 -> OUT.
template <bool BF16OUT>
__global__ __launch_bounds__(256) void agg_fin_kernel(
    const float* __restrict__ H, const float* __restrict__ bias,
    float* __restrict__ OUT, int N)
{
    int gw   = (blockIdx.x * blockDim.x + threadIdx.x) >> 5;
    int lane = threadIdx.x & 31;
    if (gw >= N) return;
    int s0 = g_off[gw], s1 = g_off[gw + 1];
    float4 acc = *(const float4*)&H[(size_t)gw * HDIM + lane * 4];  // self
    for (int j = s0; j < s1; j++) {
        int s = g_csr[j];
        float4 v = __ldg((const float4*)&H[(size_t)s * HDIM + lane * 4]);
        acc.x += v.x; acc.y += v.y; acc.z += v.z; acc.w += v.w;
    }
    float sc = g_dinv[gw];
    float4 bb = *(const float4*)&bias[lane * 4];
    acc.x = acc.x * sc + bb.x; acc.y = acc.y * sc + bb.y;
    acc.z = acc.z * sc + bb.z; acc.w = acc.w * sc + bb.w;
    if (BF16OUT) {
        acc.x = fmaxf(acc.x, 0.f); acc.y = fmaxf(acc.y, 0.f);
        acc.z = fmaxf(acc.z, 0.f); acc.w = fmaxf(acc.w, 0.f);
        split_store4(acc, g_ah, g_al, (size_t)gw * HDIM + lane * 4);
    } else {
        *(float4*)&OUT[(size_t)gw * HDIM + lane * 4] = acc;
    }
}

// ---------------- decode: logits[e] = dot(Z[a], Z[b]), 1 warp/edge -----------
__global__ __launch_bounds__(256) void decode_kernel(
    const float* __restrict__ Z, const int* __restrict__ ea,
    const int* __restrict__ eb, float* __restrict__ out, int EL)
{
    int gw   = (blockIdx.x * blockDim.x + threadIdx.x) >> 5;
    int lane = threadIdx.x & 31;
    if (gw >= EL) return;
    int i = ea[gw], j = eb[gw];
    float4 u = *(const float4*)&Z[(size_t)i * HDIM + lane * 4];
    float4 v = *(const float4*)&Z[(size_t)j * HDIM + lane * 4];
    float p = u.x * v.x + u.y * v.y + u.z * v.z + u.w * v.w;
#pragma unroll
    for (int o = 16; o; o >>= 1) p += __shfl_xor_sync(0xffffffffu, p, o);
    if (lane == 0) out[gw] = p;
}

extern "C" void kernel_launch(void* const* d_in, const int* in_sizes, int n_in,
                              void* d_out, int out_size)
{
    const float* x   = (const float*)d_in[0];
    const int*   ei  = (const int*)d_in[1];
    const int*   eli = (const int*)d_in[2];
    const float* W0  = (const float*)d_in[3];
    const float* b0  = (const float*)d_in[4];
    const float* W1  = (const float*)d_in[5];
    const float* b1  = (const float*)d_in[6];
    const float* W2  = (const float*)d_in[7];
    const float* b2  = (const float*)d_in[8];
    float* logits = (float*)d_out;

    const int N  = in_sizes[0] / 256;   // 50000
    const int E  = in_sizes[1] / 2;     // 320000
    const int EL = in_sizes[2] / 2;     // 200000
    const int* src = ei;
    const int* dst = ei + E;
    const int* la  = eli;
    const int* lb  = eli + EL;

    float *p_h, *p_feat, *p_dinv;
    __nv_bfloat16 *p_ah, *p_al;
    cudaGetSymbolAddress((void**)&p_h,    g_h);
    cudaGetSymbolAddress((void**)&p_feat, g_feat);
    cudaGetSymbolAddress((void**)&p_dinv, g_dinv);
    cudaGetSymbolAddress((void**)&p_ah,   g_ah);
    cudaGetSymbolAddress((void**)&p_al,   g_al);

    const int SMEM256 = (2 * 128 * 264 + 4 * 128 * 24) * 2;  // 159744
    const int SMEM128 = (2 * 128 * 136 + 4 * 128 * 24) * 2;  //  94208
    cudaFuncSetAttribute((gemm_mma_kernel<256, true>),
                         cudaFuncAttributeMaxDynamicSharedMemorySize, SMEM256);
    cudaFuncSetAttribute((gemm_mma_kernel<128, false>),
                         cudaFuncAttributeMaxDynamicSharedMemorySize, SMEM128);

    const int TB = 256;
    const int nscan = (N + 255) / 256;              // 196 blocks

    // degrees + CSR build (+dinv fused into scan_add)
    deg_init_kernel<<<(N + TB - 1) / TB, TB>>>(N);
    deg_count_kernel<<<512, TB>>>(dst, E);
    scan_block_kernel<<<nscan, 256>>>(N);
    scan_part_kernel<<<1, 256>>>(nscan);
    scan_add_kernel<<<nscan, 256>>>(N, E);
    csr_fill_kernel<<<512, TB>>>(src, dst, E);

    const int mtiles     = (N + 127) / 128;
    const int agg_blocks = (N + 7) / 8;             // 8 warps/block

    // Layer 0: K=256, fused fp32->bf16x2 split of x
    convert_w_kernel<<<(128 * 256 + TB - 1) / TB, TB>>>(W0, 256);
    gemm_mma_kernel<256, true><<<mtiles, TB, SMEM256>>>(
        nullptr, nullptr, x, p_h, p_dinv, N);
    agg_fin_kernel<true><<<agg_blocks, TB>>>(p_h, b0, nullptr, N);

    // Layer 1: K=128
    convert_w_kernel<<<(128 * 128 + TB - 1) / TB, TB>>>(W1, 128);
    gemm_mma_kernel<128, false><<<mtiles, TB, SMEM128>>>(
        p_ah, p_al, nullptr, p_h, p_dinv, N);
    agg_fin_kernel<true><<<agg_blocks, TB>>>(p_h, b1, nullptr, N);

    // Layer 2: K=128, no relu, fp32 out
    convert_w_kernel<<<(128 * 128 + TB - 1) / TB, TB>>>(W2, 128);
    gemm_mma_kernel<128, false><<<mtiles, TB, SMEM128>>>(
        p_ah, p_al, nullptr, p_h, p_dinv, N);
    agg_fin_kernel<false><<<agg_blocks, TB>>>(p_h, b2, p_feat, N);

    // Decode
    decode_kernel<<<(EL + 7) / 8, TB>>>(p_feat, la, lb, logits, EL);
}

// round 10
// speedup vs baseline: 1.6369x; 1.0024x over previous
#include <cuda_runtime.h>
#include <cuda_bf16.h>
#include <math.h>
#include <stdint.h>

#define NND 50000
#define EMAX 320000
#define HDIM 128

// ---------------- scratch (device globals; allocation-free contract) --------
__device__ int            g_deg[NND];
__device__ float          g_dinv[NND];
__device__ float          g_h[(size_t)NND * HDIM];
__device__ float          g_feat[(size_t)NND * HDIM];
__device__ __nv_bfloat16  g_ah[(size_t)NND * HDIM];
__device__ __nv_bfloat16  g_al[(size_t)NND * HDIM];
// W0 at [0, 32768), W1 at [32768, 49152), W2 at [49152, 65536)
__device__ __nv_bfloat16  g_wh[65536];
__device__ __nv_bfloat16  g_wl[65536];
// CSR
__device__ int g_off[NND + 1];
__device__ int g_cur[NND];
__device__ int g_csr[EMAX];
__device__ int g_part[256];

// ---------------- setup: deg init + split all three W matrices --------------
// index space: [0,50000) deg; then W0 (128x256), W1, W2 (128x128 each),
// transposed to [128,K] bf16 hi/lo.
__global__ void setup_kernel(const float* __restrict__ W0,
                             const float* __restrict__ W1,
                             const float* __restrict__ W2, int n) {
    int i = blockIdx.x * blockDim.x + threadIdx.x;
    if (i < n) { g_deg[i] = 1; return; }
    int j = i - n;
    const float* W; int K, base;
    if (j < 32768)        { W = W0; K = 256; base = 0;     }
    else if (j < 49152)   { W = W1; K = 128; base = 32768; j -= 32768; }
    else if (j < 65536)   { W = W2; K = 128; base = 49152; j -= 49152; }
    else return;
    int nn = j / K, k = j % K;
    float v = W[k * 128 + nn];
    float h = __bfloat162float(__float2bfloat16(v));
    g_wh[base + j] = __float2bfloat16(h);
    g_wl[base + j] = __float2bfloat16(v - h);
}

__global__ void deg_count_kernel(const int* __restrict__ dst, int E) {
    for (int e = blockIdx.x * blockDim.x + threadIdx.x; e < E;
         e += gridDim.x * blockDim.x)
        atomicAdd(&g_deg[dst[e]], 1);
}

// ---------------- CSR build: scan + fill -------------------------------------
__global__ void scan_block_kernel(int n) {
    __shared__ int sh[256];
    int i = blockIdx.x * 256 + threadIdx.x;
    int v = (i < n) ? g_deg[i] - 1 : 0;
    sh[threadIdx.x] = v;
    __syncthreads();
#pragma unroll
    for (int o = 1; o < 256; o <<= 1) {
        int t = (threadIdx.x >= o) ? sh[threadIdx.x - o] : 0;
        __syncthreads();
        sh[threadIdx.x] += t;
        __syncthreads();
    }
    int incl = sh[threadIdx.x];
    if (i < n) g_off[i] = incl - v;                 // block-local exclusive
    if (threadIdx.x == 255) g_part[blockIdx.x] = incl;
}
// block offset computed by direct reduction over g_part[j < bid]; +dinv fused
__global__ void scan_add_kernel(int n, int E, int nb) {
    __shared__ int sh[256];
    int t = threadIdx.x, bid = blockIdx.x;
    sh[t] = (t < nb && t < bid) ? g_part[t] : 0;
    __syncthreads();
#pragma unroll
    for (int o = 128; o; o >>= 1) {
        if (t < o) sh[t] += sh[t + o];
        __syncthreads();
    }
    int boff = sh[0];
    int i = bid * 256 + t;
    if (i < n) {
        int o = g_off[i] + boff;
        g_off[i] = o;
        g_cur[i] = o;
        g_dinv[i] = rsqrtf((float)g_deg[i]);
    }
    if (i == 0) g_off[n] = E;
}
__global__ void csr_fill_kernel(const int* __restrict__ src,
                                const int* __restrict__ dst, int E) {
    for (int e = blockIdx.x * blockDim.x + threadIdx.x; e < E;
         e += gridDim.x * blockDim.x) {
        int p = atomicAdd(&g_cur[dst[e]], 1);
        g_csr[p] = src[e];
    }
}

// ---------------- bf16 split helpers ----------------
__device__ __forceinline__ void split_store4(float4 v, __nv_bfloat16* ah,
                                             __nv_bfloat16* al, size_t off) {
    float hx = __bfloat162float(__float2bfloat16(v.x));
    float hy = __bfloat162float(__float2bfloat16(v.y));
    float hz = __bfloat162float(__float2bfloat16(v.z));
    float hw = __bfloat162float(__float2bfloat16(v.w));
    __nv_bfloat162 h01 = __floats2bfloat162_rn(hx, hy);
    __nv_bfloat162 h23 = __floats2bfloat162_rn(hz, hw);
    __nv_bfloat162 l01 = __floats2bfloat162_rn(v.x - hx, v.y - hy);
    __nv_bfloat162 l23 = __floats2bfloat162_rn(v.z - hz, v.w - hw);
    uint2 hp, lp;
    hp.x = *(uint32_t*)&h01; hp.y = *(uint32_t*)&h23;
    lp.x = *(uint32_t*)&l01; lp.y = *(uint32_t*)&l23;
    *(uint2*)&ah[off] = hp;
    *(uint2*)&al[off] = lp;
}

// ---------------- HMMA GEMM: H = (A @ W^T) * dinv[row]  (bf16x3 split) -------
#define MMA16816(d, a, b) \
    asm volatile( \
        "mma.sync.aligned.m16n8k16.row.col.f32.bf16.bf16.f32 " \
        "{%0,%1,%2,%3}, {%4,%5,%6,%7}, {%8,%9}, {%0,%1,%2,%3};" \
        : "+f"((d)[0]), "+f"((d)[1]), "+f"((d)[2]), "+f"((d)[3]) \
        : "r"((a)[0]), "r"((a)[1]), "r"((a)[2]), "r"((a)[3]), \
          "r"((b)[0]), "r"((b)[1]))

// FUSE=true: A comes from fp32 Xf (split to hi/lo in registers during copy).
template <int K, bool FUSE, int MINBLK>
__global__ __launch_bounds__(256, MINBLK) void gemm_mma_kernel(
    const __nv_bfloat16* __restrict__ Ah, const __nv_bfloat16* __restrict__ Al,
    const float* __restrict__ Xf,
    const __nv_bfloat16* __restrict__ Wh, const __nv_bfloat16* __restrict__ Wl,
    float* __restrict__ H, const float* __restrict__ dinv, int M)
{
    extern __shared__ char smem[];
    const int PW = K + 8;   // W row pitch (bf16)
    const int PA = 24;      // A row pitch (bf16)

    __nv_bfloat16* sWh = (__nv_bfloat16*)smem;
    __nv_bfloat16* sWl = sWh + 128 * PW;
    __nv_bfloat16* sA  = sWl + 128 * PW;   // [stage][buf][128][PA]

    const int tid = threadIdx.x, lane = tid & 31, wid = tid >> 5;
    const int wm = wid & 3, wn = wid >> 2;     // warp tile: 32 rows x 64 cols
    const int m0 = blockIdx.x * 128;

    const int WCH = 128 * (K / 8);
    for (int i = tid; i < WCH; i += 256) {
        int n = i / (K / 8), c = i % (K / 8);
        *(uint4*)(sWh + n * PW + c * 8) = *(const uint4*)(Wh + n * K + c * 8);
        *(uint4*)(sWl + n * PW + c * 8) = *(const uint4*)(Wl + n * K + c * 8);
    }

    auto copyA = [&](int ks, int st) {
        if (FUSE) {
            int row = tid >> 1, half = tid & 1;
            int gr = m0 + row;
            float4 v0 = make_float4(0.f, 0.f, 0.f, 0.f), v1 = v0;
            if (gr < M) {
                const float4* p = (const float4*)(Xf + (size_t)gr * K + ks * 16 + half * 8);
                v0 = p[0]; v1 = p[1];
            }
            float f[8] = {v0.x, v0.y, v0.z, v0.w, v1.x, v1.y, v1.z, v1.w};
            uint32_t hi[4], lo[4];
#pragma unroll
            for (int j = 0; j < 4; j++) {
                float a = f[2 * j], b = f[2 * j + 1];
                float ha = __bfloat162float(__float2bfloat16(a));
                float hb = __bfloat162float(__float2bfloat16(b));
                __nv_bfloat162 hh = __floats2bfloat162_rn(ha, hb);
                __nv_bfloat162 ll = __floats2bfloat162_rn(a - ha, b - hb);
                hi[j] = *(uint32_t*)&hh;
                lo[j] = *(uint32_t*)&ll;
            }
            __nv_bfloat16* dh = sA + ((st * 2 + 0) * 128 + row) * PA + half * 8;
            __nv_bfloat16* dl = sA + ((st * 2 + 1) * 128 + row) * PA + half * 8;
            *(uint4*)dh = make_uint4(hi[0], hi[1], hi[2], hi[3]);
            *(uint4*)dl = make_uint4(lo[0], lo[1], lo[2], lo[3]);
        } else {
            int buf = tid >> 7, row = tid & 127;
            int gr = m0 + row;
            const __nv_bfloat16* src = buf ? Al : Ah;
            uint4 v0 = make_uint4(0u, 0u, 0u, 0u), v1 = v0;
            if (gr < M) {
                const uint4* p = (const uint4*)(src + (size_t)gr * K + ks * 16);
                v0 = p[0]; v1 = p[1];
            }
            __nv_bfloat16* d = sA + ((st * 2 + buf) * 128 + row) * PA;
            *(uint4*)d = v0; *(uint4*)(d + 8) = v1;
        }
    };

    float acc[2][8][4];
#pragma unroll
    for (int mt = 0; mt < 2; mt++)
#pragma unroll
        for (int nt = 0; nt < 8; nt++)
#pragma unroll
            for (int j = 0; j < 4; j++) acc[mt][nt][j] = 0.f;

    const int NS = K / 16;
    copyA(0, 0);
    __syncthreads();

    const int ar0 = wm * 32 + (lane >> 2);
    const int kk  = (lane & 3) * 2;
    const int nb  = wn * 64 + (lane >> 2);

    for (int ks = 0; ks < NS; ks++) {
        int st = ks & 1;
        if (ks + 1 < NS) copyA(ks + 1, st ^ 1);

        const __nv_bfloat16* Abh = sA + (st * 2 + 0) * 128 * PA;
        const __nv_bfloat16* Abl = sA + (st * 2 + 1) * 128 * PA;

        uint32_t ah[2][4], al[2][4];
#pragma unroll
        for (int mt = 0; mt < 2; mt++) {
            int r = ar0 + mt * 16;
            ah[mt][0] = *(const uint32_t*)(Abh + r * PA + kk);
            ah[mt][1] = *(const uint32_t*)(Abh + (r + 8) * PA + kk);
            ah[mt][2] = *(const uint32_t*)(Abh + r * PA + kk + 8);
            ah[mt][3] = *(const uint32_t*)(Abh + (r + 8) * PA + kk + 8);
            al[mt][0] = *(const uint32_t*)(Abl + r * PA + kk);
            al[mt][1] = *(const uint32_t*)(Abl + (r + 8) * PA + kk);
            al[mt][2] = *(const uint32_t*)(Abl + r * PA + kk + 8);
            al[mt][3] = *(const uint32_t*)(Abl + (r + 8) * PA + kk + 8);
        }
        uint32_t bh[8][2], bl[8][2];
        int kw = ks * 16 + kk;
#pragma unroll
        for (int nt = 0; nt < 8; nt++) {
            const __nv_bfloat16* ph = sWh + (nb + nt * 8) * PW + kw;
            const __nv_bfloat16* pl = sWl + (nb + nt * 8) * PW + kw;
            bh[nt][0] = *(const uint32_t*)ph;
            bh[nt][1] = *(const uint32_t*)(ph + 8);
            bl[nt][0] = *(const uint32_t*)pl;
            bl[nt][1] = *(const uint32_t*)(pl + 8);
        }
#pragma unroll
        for (int mt = 0; mt < 2; mt++)
#pragma unroll
            for (int nt = 0; nt < 8; nt++) {
                MMA16816(acc[mt][nt], ah[mt], bh[nt]);  // hi*hi
                MMA16816(acc[mt][nt], ah[mt], bl[nt]);  // hi*lo
                MMA16816(acc[mt][nt], al[mt], bh[nt]);  // lo*hi
            }
        __syncthreads();
    }

    // ---- epilogue: scale rows by dinv, write H only ----
    const int cbase = wn * 64 + (lane & 3) * 2;
#pragma unroll
    for (int mt = 0; mt < 2; mt++) {
        int ra = m0 + wm * 32 + mt * 16 + (lane >> 2);
        int rb = ra + 8;
        float sa = (ra < M) ? dinv[ra] : 0.f;
        float sb = (rb < M) ? dinv[rb] : 0.f;
#pragma unroll
        for (int nt = 0; nt < 8; nt++) {
            int col = cbase + nt * 8;
            if (ra < M)
                *(float2*)&H[(size_t)ra * HDIM + col] =
                    make_float2(acc[mt][nt][0] * sa, acc[mt][nt][1] * sa);
            if (rb < M)
                *(float2*)&H[(size_t)rb * HDIM + col] =
                    make_float2(acc[mt][nt][2] * sb, acc[mt][nt][3] * sb);
        }
    }
}

// ---------------- fused aggregate + finalize ---------------------------------
template <bool BF16OUT>
__global__ __launch_bounds__(256) void agg_fin_kernel(
    const float* __restrict__ H, const float* __restrict__ bias,
    float* __restrict__ OUT, int N)
{
    int gw   = (blockIdx.x * blockDim.x + threadIdx.x) >> 5;
    int lane = threadIdx.x & 31;
    if (gw >= N) return;
    int s0 = g_off[gw], s1 = g_off[gw + 1];
    float4 acc = *(const float4*)&H[(size_t)gw * HDIM + lane * 4];  // self
    for (int j = s0; j < s1; j++) {
        int s = g_csr[j];
        float4 v = __ldg((const float4*)&H[(size_t)s * HDIM + lane * 4]);
        acc.x += v.x; acc.y += v.y; acc.z += v.z; acc.w += v.w;
    }
    float sc = g_dinv[gw];
    float4 bb = *(const float4*)&bias[lane * 4];
    acc.x = acc.x * sc + bb.x; acc.y = acc.y * sc + bb.y;
    acc.z = acc.z * sc + bb.z; acc.w = acc.w * sc + bb.w;
    if (BF16OUT) {
        acc.x = fmaxf(acc.x, 0.f); acc.y = fmaxf(acc.y, 0.f);
        acc.z = fmaxf(acc.z, 0.f); acc.w = fmaxf(acc.w, 0.f);
        split_store4(acc, g_ah, g_al, (size_t)gw * HDIM + lane * 4);
    } else {
        *(float4*)&OUT[(size_t)gw * HDIM + lane * 4] = acc;
    }
}

// ---------------- decode: logits[e] = dot(Z[a], Z[b]), 1 warp/edge -----------
__global__ __launch_bounds__(256) void decode_kernel(
    const float* __restrict__ Z, const int* __restrict__ ea,
    const int* __restrict__ eb, float* __restrict__ out, int EL)
{
    int gw   = (blockIdx.x * blockDim.x + threadIdx.x) >> 5;
    int lane = threadIdx.x & 31;
    if (gw >= EL) return;
    int i = ea[gw], j = eb[gw];
    float4 u = *(const float4*)&Z[(size_t)i * HDIM + lane * 4];
    float4 v = *(const float4*)&Z[(size_t)j * HDIM + lane * 4];
    float p = u.x * v.x + u.y * v.y + u.z * v.z + u.w * v.w;
#pragma unroll
    for (int o = 16; o; o >>= 1) p += __shfl_xor_sync(0xffffffffu, p, o);
    if (lane == 0) out[gw] = p;
}

extern "C" void kernel_launch(void* const* d_in, const int* in_sizes, int n_in,
                              void* d_out, int out_size)
{
    const float* x   = (const float*)d_in[0];
    const int*   ei  = (const int*)d_in[1];
    const int*   eli = (const int*)d_in[2];
    const float* W0  = (const float*)d_in[3];
    const float* b0  = (const float*)d_in[4];
    const float* W1  = (const float*)d_in[5];
    const float* b1  = (const float*)d_in[6];
    const float* W2  = (const float*)d_in[7];
    const float* b2  = (const float*)d_in[8];
    float* logits = (float*)d_out;

    const int N  = in_sizes[0] / 256;   // 50000
    const int E  = in_sizes[1] / 2;     // 320000
    const int EL = in_sizes[2] / 2;     // 200000
    const int* src = ei;
    const int* dst = ei + E;
    const int* la  = eli;
    const int* lb  = eli + EL;

    float *p_h, *p_feat, *p_dinv;
    __nv_bfloat16 *p_ah, *p_al, *p_wh, *p_wl;
    cudaGetSymbolAddress((void**)&p_h,    g_h);
    cudaGetSymbolAddress((void**)&p_feat, g_feat);
    cudaGetSymbolAddress((void**)&p_dinv, g_dinv);
    cudaGetSymbolAddress((void**)&p_ah,   g_ah);
    cudaGetSymbolAddress((void**)&p_al,   g_al);
    cudaGetSymbolAddress((void**)&p_wh,   g_wh);
    cudaGetSymbolAddress((void**)&p_wl,   g_wl);

    const int SMEM256 = (2 * 128 * 264 + 4 * 128 * 24) * 2;  // 159744
    const int SMEM128 = (2 * 128 * 136 + 4 * 128 * 24) * 2;  //  94208
    cudaFuncSetAttribute((gemm_mma_kernel<256, true, 1>),
                         cudaFuncAttributeMaxDynamicSharedMemorySize, SMEM256);
    cudaFuncSetAttribute((gemm_mma_kernel<128, false, 2>),
                         cudaFuncAttributeMaxDynamicSharedMemorySize, SMEM128);

    const int TB = 256;
    const int nscan = (N + 255) / 256;              // 196 blocks

    // setup (deg init + all W splits), degrees, CSR
    const int setup_items = N + 65536;
    setup_kernel<<<(setup_items + TB - 1) / TB, TB>>>(W0, W1, W2, N);
    deg_count_kernel<<<512, TB>>>(dst, E);
    scan_block_kernel<<<nscan, 256>>>(N);
    scan_add_kernel<<<nscan, 256>>>(N, E, nscan);
    csr_fill_kernel<<<512, TB>>>(src, dst, E);

    const int mtiles     = (N + 127) / 128;
    const int agg_blocks = (N + 7) / 8;             // 8 warps/block

    // Layer 0: K=256, fused fp32->bf16x2 split of x
    gemm_mma_kernel<256, true, 1><<<mtiles, TB, SMEM256>>>(
        nullptr, nullptr, x, p_wh, p_wl, p_h, p_dinv, N);
    agg_fin_kernel<true><<<agg_blocks, TB>>>(p_h, b0, nullptr, N);

    // Layer 1: K=128
    gemm_mma_kernel<128, false, 2><<<mtiles, TB, SMEM128>>>(
        p_ah, p_al, nullptr, p_wh + 32768, p_wl + 32768, p_h, p_dinv, N);
    agg_fin_kernel<true><<<agg_blocks, TB>>>(p_h, b1, nullptr, N);

    // Layer 2: K=128, no relu, fp32 out
    gemm_mma_kernel<128, false, 2><<<mtiles, TB, SMEM128>>>(
        p_ah, p_al, nullptr, p_wh + 49152, p_wl + 49152, p_h, p_dinv, N);
    agg_fin_kernel<false><<<agg_blocks, TB>>>(p_h, b2, p_feat, N);

    // Decode
    decode_kernel<<<(EL + 7) / 8, TB>>>(p_feat, la, lb, logits, EL);
}

// round 11
// speedup vs baseline: 1.6935x; 1.0346x over previous
#include <cuda_runtime.h>
#include <cuda_bf16.h>
#include <math.h>
#include <stdint.h>

#define NND 50000
#define EMAX 320000
#define HDIM 128

// ---------------- scratch (device globals; allocation-free contract) --------
__device__ int            g_deg[NND];
__device__ float          g_dinv[NND];
__device__ float          g_h[(size_t)NND * HDIM];
__device__ float          g_feat[(size_t)NND * HDIM];
__device__ __nv_bfloat16  g_ah[(size_t)NND * HDIM];
__device__ __nv_bfloat16  g_al[(size_t)NND * HDIM];
// W0 at [0, 32768), W1 at [32768, 49152), W2 at [49152, 65536)
__device__ __nv_bfloat16  g_wh[65536];
__device__ __nv_bfloat16  g_wl[65536];
// CSR
__device__ int g_off[NND + 1];
__device__ int g_cur[NND];
__device__ int g_csr[EMAX];
__device__ int g_part[256];

// ---------------- W split (main branch) --------------------------------------
__global__ void convw_kernel(const float* __restrict__ W0,
                             const float* __restrict__ W1,
                             const float* __restrict__ W2) {
    int j = blockIdx.x * blockDim.x + threadIdx.x;
    if (j >= 65536) return;
    const float* W; int K, jj = j;
    if (j < 32768)      { W = W0; K = 256; }
    else if (j < 49152) { W = W1; K = 128; jj -= 32768; }
    else                { W = W2; K = 128; jj -= 49152; }
    int nn = jj / K, k = jj % K;
    float v = W[k * 128 + nn];
    float h = __bfloat162float(__float2bfloat16(v));
    g_wh[j] = __float2bfloat16(h);
    g_wl[j] = __float2bfloat16(v - h);
}

// ---------------- degree / CSR (side branch) ----------------------------------
__global__ void deg_init_kernel(int n) {
    int i = blockIdx.x * blockDim.x + threadIdx.x;
    if (i < n) g_deg[i] = 1;  // self-loop
}
__global__ void deg_count_kernel(const int* __restrict__ dst, int E) {
    for (int e = blockIdx.x * blockDim.x + threadIdx.x; e < E;
         e += gridDim.x * blockDim.x)
        atomicAdd(&g_deg[dst[e]], 1);
}
__global__ void scan_block_kernel(int n) {
    __shared__ int sh[256];
    int i = blockIdx.x * 256 + threadIdx.x;
    int v = (i < n) ? g_deg[i] - 1 : 0;
    sh[threadIdx.x] = v;
    __syncthreads();
#pragma unroll
    for (int o = 1; o < 256; o <<= 1) {
        int t = (threadIdx.x >= o) ? sh[threadIdx.x - o] : 0;
        __syncthreads();
        sh[threadIdx.x] += t;
        __syncthreads();
    }
    int incl = sh[threadIdx.x];
    if (i < n) g_off[i] = incl - v;                 // block-local exclusive
    if (threadIdx.x == 255) g_part[blockIdx.x] = incl;
}
// block offset: warp 0 reduces g_part[j < bid]; +dinv fused
__global__ void scan_add_kernel(int n, int E, int nb) {
    __shared__ int s_boff;
    int t = threadIdx.x, bid = blockIdx.x;
    if (t < 32) {
        int acc = 0;
        for (int j = t; j < bid; j += 32) acc += g_part[j];
#pragma unroll
        for (int o = 16; o; o >>= 1) acc += __shfl_xor_sync(0xffffffffu, acc, o);
        if (t == 0) s_boff = acc;
    }
    __syncthreads();
    int i = bid * 256 + t;
    if (i < n) {
        int o = g_off[i] + s_boff;
        g_off[i] = o;
        g_cur[i] = o;
        g_dinv[i] = rsqrtf((float)g_deg[i]);
    }
    if (i == 0) g_off[n] = E;
}
__global__ void csr_fill_kernel(const int* __restrict__ src,
                                const int* __restrict__ dst, int E) {
    for (int e = blockIdx.x * blockDim.x + threadIdx.x; e < E;
         e += gridDim.x * blockDim.x) {
        int p = atomicAdd(&g_cur[dst[e]], 1);
        g_csr[p] = src[e];
    }
}

// ---------------- bf16 split helpers ----------------
__device__ __forceinline__ void split_store4(float4 v, __nv_bfloat16* ah,
                                             __nv_bfloat16* al, size_t off) {
    float hx = __bfloat162float(__float2bfloat16(v.x));
    float hy = __bfloat162float(__float2bfloat16(v.y));
    float hz = __bfloat162float(__float2bfloat16(v.z));
    float hw = __bfloat162float(__float2bfloat16(v.w));
    __nv_bfloat162 h01 = __floats2bfloat162_rn(hx, hy);
    __nv_bfloat162 h23 = __floats2bfloat162_rn(hz, hw);
    __nv_bfloat162 l01 = __floats2bfloat162_rn(v.x - hx, v.y - hy);
    __nv_bfloat162 l23 = __floats2bfloat162_rn(v.z - hz, v.w - hw);
    uint2 hp, lp;
    hp.x = *(uint32_t*)&h01; hp.y = *(uint32_t*)&h23;
    lp.x = *(uint32_t*)&l01; lp.y = *(uint32_t*)&l23;
    *(uint2*)&ah[off] = hp;
    *(uint2*)&al[off] = lp;
}

// ---------------- HMMA GEMM: H = A @ W^T  (bf16x3 split, raw, no dinv) -------
#define MMA16816(d, a, b) \
    asm volatile( \
        "mma.sync.aligned.m16n8k16.row.col.f32.bf16.bf16.f32 " \
        "{%0,%1,%2,%3}, {%4,%5,%6,%7}, {%8,%9}, {%0,%1,%2,%3};" \
        : "+f"((d)[0]), "+f"((d)[1]), "+f"((d)[2]), "+f"((d)[3]) \
        : "r"((a)[0]), "r"((a)[1]), "r"((a)[2]), "r"((a)[3]), \
          "r"((b)[0]), "r"((b)[1]))

// FUSE=true: A comes from fp32 Xf (split to hi/lo in registers during copy).
template <int K, bool FUSE, int MINBLK>
__global__ __launch_bounds__(256, MINBLK) void gemm_mma_kernel(
    const __nv_bfloat16* __restrict__ Ah, const __nv_bfloat16* __restrict__ Al,
    const float* __restrict__ Xf,
    const __nv_bfloat16* __restrict__ Wh, const __nv_bfloat16* __restrict__ Wl,
    float* __restrict__ H, int M)
{
    extern __shared__ char smem[];
    const int PW = K + 8;   // W row pitch (bf16)
    const int PA = 24;      // A row pitch (bf16)

    __nv_bfloat16* sWh = (__nv_bfloat16*)smem;
    __nv_bfloat16* sWl = sWh + 128 * PW;
    __nv_bfloat16* sA  = sWl + 128 * PW;   // [stage][buf][128][PA]

    const int tid = threadIdx.x, lane = tid & 31, wid = tid >> 5;
    const int wm = wid & 3, wn = wid >> 2;     // warp tile: 32 rows x 64 cols
    const int m0 = blockIdx.x * 128;

    const int WCH = 128 * (K / 8);
    for (int i = tid; i < WCH; i += 256) {
        int n = i / (K / 8), c = i % (K / 8);
        *(uint4*)(sWh + n * PW + c * 8) = *(const uint4*)(Wh + n * K + c * 8);
        *(uint4*)(sWl + n * PW + c * 8) = *(const uint4*)(Wl + n * K + c * 8);
    }

    auto copyA = [&](int ks, int st) {
        if (FUSE) {
            int row = tid >> 1, half = tid & 1;
            int gr = m0 + row;
            float4 v0 = make_float4(0.f, 0.f, 0.f, 0.f), v1 = v0;
            if (gr < M) {
                const float4* p = (const float4*)(Xf + (size_t)gr * K + ks * 16 + half * 8);
                v0 = p[0]; v1 = p[1];
            }
            float f[8] = {v0.x, v0.y, v0.z, v0.w, v1.x, v1.y, v1.z, v1.w};
            uint32_t hi[4], lo[4];
#pragma unroll
            for (int j = 0; j < 4; j++) {
                float a = f[2 * j], b = f[2 * j + 1];
                float ha = __bfloat162float(__float2bfloat16(a));
                float hb = __bfloat162float(__float2bfloat16(b));
                __nv_bfloat162 hh = __floats2bfloat162_rn(ha, hb);
                __nv_bfloat162 ll = __floats2bfloat162_rn(a - ha, b - hb);
                hi[j] = *(uint32_t*)&hh;
                lo[j] = *(uint32_t*)&ll;
            }
            __nv_bfloat16* dh = sA + ((st * 2 + 0) * 128 + row) * PA + half * 8;
            __nv_bfloat16* dl = sA + ((st * 2 + 1) * 128 + row) * PA + half * 8;
            *(uint4*)dh = make_uint4(hi[0], hi[1], hi[2], hi[3]);
            *(uint4*)dl = make_uint4(lo[0], lo[1], lo[2], lo[3]);
        } else {
            int buf = tid >> 7, row = tid & 127;
            int gr = m0 + row;
            const __nv_bfloat16* src = buf ? Al : Ah;
            uint4 v0 = make_uint4(0u, 0u, 0u, 0u), v1 = v0;
            if (gr < M) {
                const uint4* p = (const uint4*)(src + (size_t)gr * K + ks * 16);
                v0 = p[0]; v1 = p[1];
            }
            __nv_bfloat16* d = sA + ((st * 2 + buf) * 128 + row) * PA;
            *(uint4*)d = v0; *(uint4*)(d + 8) = v1;
        }
    };

    float acc[2][8][4];
#pragma unroll
    for (int mt = 0; mt < 2; mt++)
#pragma unroll
        for (int nt = 0; nt < 8; nt++)
#pragma unroll
            for (int j = 0; j < 4; j++) acc[mt][nt][j] = 0.f;

    const int NS = K / 16;
    copyA(0, 0);
    __syncthreads();

    const int ar0 = wm * 32 + (lane >> 2);
    const int kk  = (lane & 3) * 2;
    const int nb  = wn * 64 + (lane >> 2);

    for (int ks = 0; ks < NS; ks++) {
        int st = ks & 1;
        if (ks + 1 < NS) copyA(ks + 1, st ^ 1);

        const __nv_bfloat16* Abh = sA + (st * 2 + 0) * 128 * PA;
        const __nv_bfloat16* Abl = sA + (st * 2 + 1) * 128 * PA;

        uint32_t ah[2][4], al[2][4];
#pragma unroll
        for (int mt = 0; mt < 2; mt++) {
            int r = ar0 + mt * 16;
            ah[mt][0] = *(const uint32_t*)(Abh + r * PA + kk);
            ah[mt][1] = *(const uint32_t*)(Abh + (r + 8) * PA + kk);
            ah[mt][2] = *(const uint32_t*)(Abh + r * PA + kk + 8);
            ah[mt][3] = *(const uint32_t*)(Abh + (r + 8) * PA + kk + 8);
            al[mt][0] = *(const uint32_t*)(Abl + r * PA + kk);
            al[mt][1] = *(const uint32_t*)(Abl + (r + 8) * PA + kk);
            al[mt][2] = *(const uint32_t*)(Abl + r * PA + kk + 8);
            al[mt][3] = *(const uint32_t*)(Abl + (r + 8) * PA + kk + 8);
        }
        uint32_t bh[8][2], bl[8][2];
        int kw = ks * 16 + kk;
#pragma unroll
        for (int nt = 0; nt < 8; nt++) {
            const __nv_bfloat16* ph = sWh + (nb + nt * 8) * PW + kw;
            const __nv_bfloat16* pl = sWl + (nb + nt * 8) * PW + kw;
            bh[nt][0] = *(const uint32_t*)ph;
            bh[nt][1] = *(const uint32_t*)(ph + 8);
            bl[nt][0] = *(const uint32_t*)pl;
            bl[nt][1] = *(const uint32_t*)(pl + 8);
        }
#pragma unroll
        for (int mt = 0; mt < 2; mt++)
#pragma unroll
            for (int nt = 0; nt < 8; nt++) {
                MMA16816(acc[mt][nt], ah[mt], bh[nt]);  // hi*hi
                MMA16816(acc[mt][nt], ah[mt], bl[nt]);  // hi*lo
                MMA16816(acc[mt][nt], al[mt], bh[nt]);  // lo*hi
            }
        __syncthreads();
    }

    // ---- epilogue: write raw H ----
    const int cbase = wn * 64 + (lane & 3) * 2;
#pragma unroll
    for (int mt = 0; mt < 2; mt++) {
        int ra = m0 + wm * 32 + mt * 16 + (lane >> 2);
        int rb = ra + 8;
#pragma unroll
        for (int nt = 0; nt < 8; nt++) {
            int col = cbase + nt * 8;
            if (ra < M)
                *(float2*)&H[(size_t)ra * HDIM + col] =
                    make_float2(acc[mt][nt][0], acc[mt][nt][1]);
            if (rb < M)
                *(float2*)&H[(size_t)rb * HDIM + col] =
                    make_float2(acc[mt][nt][2], acc[mt][nt][3]);
        }
    }
}

// ---------------- fused aggregate + finalize (per-message dinv) --------------
// inner = dinv[d]*H[d] + sum_s dinv[s]*H[s];  out = inner*dinv[d] + b; [relu]
template <bool BF16OUT>
__global__ __launch_bounds__(256) void agg_fin_kernel(
    const float* __restrict__ H, const float* __restrict__ bias,
    float* __restrict__ OUT, int N)
{
    int gw   = (blockIdx.x * blockDim.x + threadIdx.x) >> 5;
    int lane = threadIdx.x & 31;
    if (gw >= N) return;
    int s0 = g_off[gw], s1 = g_off[gw + 1];
    float di = g_dinv[gw];
    float4 acc = *(const float4*)&H[(size_t)gw * HDIM + lane * 4];  // self
    acc.x *= di; acc.y *= di; acc.z *= di; acc.w *= di;
    for (int j = s0; j < s1; j++) {
        int s = g_csr[j];
        float ds = __ldg(&g_dinv[s]);
        float4 v = __ldg((const float4*)&H[(size_t)s * HDIM + lane * 4]);
        acc.x = fmaf(v.x, ds, acc.x); acc.y = fmaf(v.y, ds, acc.y);
        acc.z = fmaf(v.z, ds, acc.z); acc.w = fmaf(v.w, ds, acc.w);
    }
    float4 bb = *(const float4*)&bias[lane * 4];
    acc.x = acc.x * di + bb.x; acc.y = acc.y * di + bb.y;
    acc.z = acc.z * di + bb.z; acc.w = acc.w * di + bb.w;
    if (BF16OUT) {
        acc.x = fmaxf(acc.x, 0.f); acc.y = fmaxf(acc.y, 0.f);
        acc.z = fmaxf(acc.z, 0.f); acc.w = fmaxf(acc.w, 0.f);
        split_store4(acc, g_ah, g_al, (size_t)gw * HDIM + lane * 4);
    } else {
        *(float4*)&OUT[(size_t)gw * HDIM + lane * 4] = acc;
    }
}

// ---------------- decode: logits[e] = dot(Z[a], Z[b]), 1 warp/edge -----------
__global__ __launch_bounds__(256) void decode_kernel(
    const float* __restrict__ Z, const int* __restrict__ ea,
    const int* __restrict__ eb, float* __restrict__ out, int EL)
{
    int gw   = (blockIdx.x * blockDim.x + threadIdx.x) >> 5;
    int lane = threadIdx.x & 31;
    if (gw >= EL) return;
    int i = ea[gw], j = eb[gw];
    float4 u = *(const float4*)&Z[(size_t)i * HDIM + lane * 4];
    float4 v = *(const float4*)&Z[(size_t)j * HDIM + lane * 4];
    float p = u.x * v.x + u.y * v.y + u.z * v.z + u.w * v.w;
#pragma unroll
    for (int o = 16; o; o >>= 1) p += __shfl_xor_sync(0xffffffffu, p, o);
    if (lane == 0) out[gw] = p;
}

extern "C" void kernel_launch(void* const* d_in, const int* in_sizes, int n_in,
                              void* d_out, int out_size)
{
    const float* x   = (const float*)d_in[0];
    const int*   ei  = (const int*)d_in[1];
    const int*   eli = (const int*)d_in[2];
    const float* W0  = (const float*)d_in[3];
    const float* b0  = (const float*)d_in[4];
    const float* W1  = (const float*)d_in[5];
    const float* b1  = (const float*)d_in[6];
    const float* W2  = (const float*)d_in[7];
    const float* b2  = (const float*)d_in[8];
    float* logits = (float*)d_out;

    const int N  = in_sizes[0] / 256;   // 50000
    const int E  = in_sizes[1] / 2;     // 320000
    const int EL = in_sizes[2] / 2;     // 200000
    const int* src = ei;
    const int* dst = ei + E;
    const int* la  = eli;
    const int* lb  = eli + EL;

    float *p_h, *p_feat;
    __nv_bfloat16 *p_ah, *p_al, *p_wh, *p_wl;
    cudaGetSymbolAddress((void**)&p_h,    g_h);
    cudaGetSymbolAddress((void**)&p_feat, g_feat);
    cudaGetSymbolAddress((void**)&p_ah,   g_ah);
    cudaGetSymbolAddress((void**)&p_al,   g_al);
    cudaGetSymbolAddress((void**)&p_wh,   g_wh);
    cudaGetSymbolAddress((void**)&p_wl,   g_wl);

    const int SMEM256 = (2 * 128 * 264 + 4 * 128 * 24) * 2;  // 159744
    const int SMEM128 = (2 * 128 * 136 + 4 * 128 * 24) * 2;  //  94208
    cudaFuncSetAttribute((gemm_mma_kernel<256, true, 1>),
                         cudaFuncAttributeMaxDynamicSharedMemorySize, SMEM256);
    cudaFuncSetAttribute((gemm_mma_kernel<128, false, 2>),
                         cudaFuncAttributeMaxDynamicSharedMemorySize, SMEM128);

    // side stream + events for fork-join (host objects, created once)
    static cudaStream_t s_side = nullptr;
    static cudaEvent_t  s_ev0 = nullptr, s_ev1 = nullptr;
    if (s_side == nullptr) {
        cudaStreamCreateWithFlags(&s_side, cudaStreamNonBlocking);
        cudaEventCreateWithFlags(&s_ev0, cudaEventDisableTiming);
        cudaEventCreateWithFlags(&s_ev1, cudaEventDisableTiming);
    }

    const int TB = 256;
    const int nscan      = (N + 255) / 256;
    const int mtiles     = (N + 127) / 128;
    const int agg_blocks = (N + 7) / 8;

    // ---- fork: side branch builds degrees + CSR + dinv ----
    cudaEventRecord(s_ev0, 0);
    cudaStreamWaitEvent(s_side, s_ev0, 0);
    deg_init_kernel<<<(N + TB - 1) / TB, TB, 0, s_side>>>(N);
    deg_count_kernel<<<512, TB, 0, s_side>>>(dst, E);
    scan_block_kernel<<<nscan, 256, 0, s_side>>>(N);
    scan_add_kernel<<<nscan, 256, 0, s_side>>>(N, E, nscan);
    csr_fill_kernel<<<512, TB, 0, s_side>>>(src, dst, E);
    cudaEventRecord(s_ev1, s_side);

    // ---- main branch: W split + layer-0 GEMM (no dinv dependency) ----
    convw_kernel<<<(65536 + TB - 1) / TB, TB>>>(W0, W1, W2);
    gemm_mma_kernel<256, true, 1><<<mtiles, TB, SMEM256>>>(
        nullptr, nullptr, x, p_wh, p_wl, p_h, N);

    // ---- join ----
    cudaStreamWaitEvent(0, s_ev1, 0);

    agg_fin_kernel<true><<<agg_blocks, TB>>>(p_h, b0, nullptr, N);

    // Layer 1: K=128
    gemm_mma_kernel<128, false, 2><<<mtiles, TB, SMEM128>>>(
        p_ah, p_al, nullptr, p_wh + 32768, p_wl + 32768, p_h, N);
    agg_fin_kernel<true><<<agg_blocks, TB>>>(p_h, b1, N ? nullptr : nullptr, N);

    // Layer 2: K=128, no relu, fp32 out
    gemm_mma_kernel<128, false, 2><<<mtiles, TB, SMEM128>>>(
        p_ah, p_al, nullptr, p_wh + 49152, p_wl + 49152, p_h, N);
    agg_fin_kernel<false><<<agg_blocks, TB>>>(p_h, b2, p_feat, N);

    // Decode
    decode_kernel<<<(EL + 7) / 8, TB>>>(p_feat, la, lb, logits, EL);
}

// round 12
// speedup vs baseline: 1.6973x; 1.0022x over previous
#include <cuda_runtime.h>
#include <cuda_bf16.h>
#include <cuda_fp16.h>
#include <math.h>
#include <stdint.h>

#define NND 50000
#define EMAX 320000
#define HDIM 128

// ---------------- scratch (device globals; allocation-free contract) --------
__device__ int            g_deg[NND];
__device__ float          g_dinv[NND];
__device__ __half         g_h[(size_t)NND * HDIM];     // fp16 message buffer
__device__ float          g_feat[(size_t)NND * HDIM];  // final z (fp32)
__device__ __nv_bfloat16  g_ah[(size_t)NND * HDIM];
__device__ __nv_bfloat16  g_al[(size_t)NND * HDIM];
// W0 at [0, 32768), W1 at [32768, 49152), W2 at [49152, 65536)
__device__ __nv_bfloat16  g_wh[65536];
__device__ __nv_bfloat16  g_wl[65536];
// CSR
__device__ int g_off[NND + 1];
__device__ int g_cur[NND];
__device__ int g_csr[EMAX];
__device__ int g_part[256];

// ---------------- W split (main branch) --------------------------------------
__global__ void convw_kernel(const float* __restrict__ W0,
                             const float* __restrict__ W1,
                             const float* __restrict__ W2) {
    int j = blockIdx.x * blockDim.x + threadIdx.x;
    if (j >= 65536) return;
    const float* W; int K, jj = j;
    if (j < 32768)      { W = W0; K = 256; }
    else if (j < 49152) { W = W1; K = 128; jj -= 32768; }
    else                { W = W2; K = 128; jj -= 49152; }
    int nn = jj / K, k = jj % K;
    float v = W[k * 128 + nn];
    float h = __bfloat162float(__float2bfloat16(v));
    g_wh[j] = __float2bfloat16(h);
    g_wl[j] = __float2bfloat16(v - h);
}

// ---------------- degree / CSR (side branch) ----------------------------------
__global__ void deg_init_kernel(int n) {
    int i = blockIdx.x * blockDim.x + threadIdx.x;
    if (i < n) g_deg[i] = 1;  // self-loop
}
__global__ void deg_count_kernel(const int* __restrict__ dst, int E) {
    for (int e = blockIdx.x * blockDim.x + threadIdx.x; e < E;
         e += gridDim.x * blockDim.x)
        atomicAdd(&g_deg[dst[e]], 1);
}
__global__ void scan_block_kernel(int n) {
    __shared__ int sh[256];
    int i = blockIdx.x * 256 + threadIdx.x;
    int v = (i < n) ? g_deg[i] - 1 : 0;
    sh[threadIdx.x] = v;
    __syncthreads();
#pragma unroll
    for (int o = 1; o < 256; o <<= 1) {
        int t = (threadIdx.x >= o) ? sh[threadIdx.x - o] : 0;
        __syncthreads();
        sh[threadIdx.x] += t;
        __syncthreads();
    }
    int incl = sh[threadIdx.x];
    if (i < n) g_off[i] = incl - v;                 // block-local exclusive
    if (threadIdx.x == 255) g_part[blockIdx.x] = incl;
}
// block offset: warp 0 reduces g_part[j < bid]; +dinv fused
__global__ void scan_add_kernel(int n, int E, int nb) {
    __shared__ int s_boff;
    int t = threadIdx.x, bid = blockIdx.x;
    if (t < 32) {
        int acc = 0;
        for (int j = t; j < bid; j += 32) acc += g_part[j];
#pragma unroll
        for (int o = 16; o; o >>= 1) acc += __shfl_xor_sync(0xffffffffu, acc, o);
        if (t == 0) s_boff = acc;
    }
    __syncthreads();
    int i = bid * 256 + t;
    if (i < n) {
        int o = g_off[i] + s_boff;
        g_off[i] = o;
        g_cur[i] = o;
        g_dinv[i] = rsqrtf((float)g_deg[i]);
    }
    if (i == 0) g_off[n] = E;
}
__global__ void csr_fill_kernel(const int* __restrict__ src,
                                const int* __restrict__ dst, int E) {
    for (int e = blockIdx.x * blockDim.x + threadIdx.x; e < E;
         e += gridDim.x * blockDim.x) {
        int p = atomicAdd(&g_cur[dst[e]], 1);
        g_csr[p] = src[e];
    }
}

// ---------------- bf16 split helpers ----------------
__device__ __forceinline__ void split_store4(float4 v, __nv_bfloat16* ah,
                                             __nv_bfloat16* al, size_t off) {
    float hx = __bfloat162float(__float2bfloat16(v.x));
    float hy = __bfloat162float(__float2bfloat16(v.y));
    float hz = __bfloat162float(__float2bfloat16(v.z));
    float hw = __bfloat162float(__float2bfloat16(v.w));
    __nv_bfloat162 h01 = __floats2bfloat162_rn(hx, hy);
    __nv_bfloat162 h23 = __floats2bfloat162_rn(hz, hw);
    __nv_bfloat162 l01 = __floats2bfloat162_rn(v.x - hx, v.y - hy);
    __nv_bfloat162 l23 = __floats2bfloat162_rn(v.z - hz, v.w - hw);
    uint2 hp, lp;
    hp.x = *(uint32_t*)&h01; hp.y = *(uint32_t*)&h23;
    lp.x = *(uint32_t*)&l01; lp.y = *(uint32_t*)&l23;
    *(uint2*)&ah[off] = hp;
    *(uint2*)&al[off] = lp;
}

// ---------------- HMMA GEMM: H(fp16) = A @ W^T  (bf16x3 split, raw) ----------
#define MMA16816(d, a, b) \
    asm volatile( \
        "mma.sync.aligned.m16n8k16.row.col.f32.bf16.bf16.f32 " \
        "{%0,%1,%2,%3}, {%4,%5,%6,%7}, {%8,%9}, {%0,%1,%2,%3};" \
        : "+f"((d)[0]), "+f"((d)[1]), "+f"((d)[2]), "+f"((d)[3]) \
        : "r"((a)[0]), "r"((a)[1]), "r"((a)[2]), "r"((a)[3]), \
          "r"((b)[0]), "r"((b)[1]))

// FUSE=true: A comes from fp32 Xf (split to hi/lo in registers during copy).
template <int K, bool FUSE, int MINBLK>
__global__ __launch_bounds__(256, MINBLK) void gemm_mma_kernel(
    const __nv_bfloat16* __restrict__ Ah, const __nv_bfloat16* __restrict__ Al,
    const float* __restrict__ Xf,
    const __nv_bfloat16* __restrict__ Wh, const __nv_bfloat16* __restrict__ Wl,
    __half* __restrict__ H, int M)
{
    extern __shared__ char smem[];
    const int PW = K + 8;   // W row pitch (bf16)
    const int PA = 24;      // A row pitch (bf16)

    __nv_bfloat16* sWh = (__nv_bfloat16*)smem;
    __nv_bfloat16* sWl = sWh + 128 * PW;
    __nv_bfloat16* sA  = sWl + 128 * PW;   // [stage][buf][128][PA]

    const int tid = threadIdx.x, lane = tid & 31, wid = tid >> 5;
    const int wm = wid & 3, wn = wid >> 2;     // warp tile: 32 rows x 64 cols
    const int m0 = blockIdx.x * 128;

    const int WCH = 128 * (K / 8);
    for (int i = tid; i < WCH; i += 256) {
        int n = i / (K / 8), c = i % (K / 8);
        *(uint4*)(sWh + n * PW + c * 8) = *(const uint4*)(Wh + n * K + c * 8);
        *(uint4*)(sWl + n * PW + c * 8) = *(const uint4*)(Wl + n * K + c * 8);
    }

    auto copyA = [&](int ks, int st) {
        if (FUSE) {
            int row = tid >> 1, half = tid & 1;
            int gr = m0 + row;
            float4 v0 = make_float4(0.f, 0.f, 0.f, 0.f), v1 = v0;
            if (gr < M) {
                const float4* p = (const float4*)(Xf + (size_t)gr * K + ks * 16 + half * 8);
                v0 = p[0]; v1 = p[1];
            }
            float f[8] = {v0.x, v0.y, v0.z, v0.w, v1.x, v1.y, v1.z, v1.w};
            uint32_t hi[4], lo[4];
#pragma unroll
            for (int j = 0; j < 4; j++) {
                float a = f[2 * j], b = f[2 * j + 1];
                float ha = __bfloat162float(__float2bfloat16(a));
                float hb = __bfloat162float(__float2bfloat16(b));
                __nv_bfloat162 hh = __floats2bfloat162_rn(ha, hb);
                __nv_bfloat162 ll = __floats2bfloat162_rn(a - ha, b - hb);
                hi[j] = *(uint32_t*)&hh;
                lo[j] = *(uint32_t*)&ll;
            }
            __nv_bfloat16* dh = sA + ((st * 2 + 0) * 128 + row) * PA + half * 8;
            __nv_bfloat16* dl = sA + ((st * 2 + 1) * 128 + row) * PA + half * 8;
            *(uint4*)dh = make_uint4(hi[0], hi[1], hi[2], hi[3]);
            *(uint4*)dl = make_uint4(lo[0], lo[1], lo[2], lo[3]);
        } else {
            int buf = tid >> 7, row = tid & 127;
            int gr = m0 + row;
            const __nv_bfloat16* src = buf ? Al : Ah;
            uint4 v0 = make_uint4(0u, 0u, 0u, 0u), v1 = v0;
            if (gr < M) {
                const uint4* p = (const uint4*)(src + (size_t)gr * K + ks * 16);
                v0 = p[0]; v1 = p[1];
            }
            __nv_bfloat16* d = sA + ((st * 2 + buf) * 128 + row) * PA;
            *(uint4*)d = v0; *(uint4*)(d + 8) = v1;
        }
    };

    float acc[2][8][4];
#pragma unroll
    for (int mt = 0; mt < 2; mt++)
#pragma unroll
        for (int nt = 0; nt < 8; nt++)
#pragma unroll
            for (int j = 0; j < 4; j++) acc[mt][nt][j] = 0.f;

    const int NS = K / 16;
    copyA(0, 0);
    __syncthreads();

    const int ar0 = wm * 32 + (lane >> 2);
    const int kk  = (lane & 3) * 2;
    const int nb  = wn * 64 + (lane >> 2);

    for (int ks = 0; ks < NS; ks++) {
        int st = ks & 1;
        if (ks + 1 < NS) copyA(ks + 1, st ^ 1);

        const __nv_bfloat16* Abh = sA + (st * 2 + 0) * 128 * PA;
        const __nv_bfloat16* Abl = sA + (st * 2 + 1) * 128 * PA;

        uint32_t ah[2][4], al[2][4];
#pragma unroll
        for (int mt = 0; mt < 2; mt++) {
            int r = ar0 + mt * 16;
            ah[mt][0] = *(const uint32_t*)(Abh + r * PA + kk);
            ah[mt][1] = *(const uint32_t*)(Abh + (r + 8) * PA + kk);
            ah[mt][2] = *(const uint32_t*)(Abh + r * PA + kk + 8);
            ah[mt][3] = *(const uint32_t*)(Abh + (r + 8) * PA + kk + 8);
            al[mt][0] = *(const uint32_t*)(Abl + r * PA + kk);
            al[mt][1] = *(const uint32_t*)(Abl + (r + 8) * PA + kk);
            al[mt][2] = *(const uint32_t*)(Abl + r * PA + kk + 8);
            al[mt][3] = *(const uint32_t*)(Abl + (r + 8) * PA + kk + 8);
        }
        uint32_t bh[8][2], bl[8][2];
        int kw = ks * 16 + kk;
#pragma unroll
        for (int nt = 0; nt < 8; nt++) {
            const __nv_bfloat16* ph = sWh + (nb + nt * 8) * PW + kw;
            const __nv_bfloat16* pl = sWl + (nb + nt * 8) * PW + kw;
            bh[nt][0] = *(const uint32_t*)ph;
            bh[nt][1] = *(const uint32_t*)(ph + 8);
            bl[nt][0] = *(const uint32_t*)pl;
            bl[nt][1] = *(const uint32_t*)(pl + 8);
        }
#pragma unroll
        for (int mt = 0; mt < 2; mt++)
#pragma unroll
            for (int nt = 0; nt < 8; nt++) {
                MMA16816(acc[mt][nt], ah[mt], bh[nt]);  // hi*hi
                MMA16816(acc[mt][nt], ah[mt], bl[nt]);  // hi*lo
                MMA16816(acc[mt][nt], al[mt], bh[nt]);  // lo*hi
            }
        __syncthreads();
    }

    // ---- epilogue: write raw H as fp16 ----
    const int cbase = wn * 64 + (lane & 3) * 2;
#pragma unroll
    for (int mt = 0; mt < 2; mt++) {
        int ra = m0 + wm * 32 + mt * 16 + (lane >> 2);
        int rb = ra + 8;
#pragma unroll
        for (int nt = 0; nt < 8; nt++) {
            int col = cbase + nt * 8;
            if (ra < M)
                *(__half2*)&H[(size_t)ra * HDIM + col] =
                    __floats2half2_rn(acc[mt][nt][0], acc[mt][nt][1]);
            if (rb < M)
                *(__half2*)&H[(size_t)rb * HDIM + col] =
                    __floats2half2_rn(acc[mt][nt][2], acc[mt][nt][3]);
        }
    }
}

// ---------------- fused aggregate + finalize (fp16 messages) -----------------
// inner = dinv[d]*H[d] + sum_s dinv[s]*H[s];  out = inner*dinv[d] + b; [relu]
template <bool BF16OUT>
__global__ __launch_bounds__(256) void agg_fin_kernel(
    const __half* __restrict__ H, const float* __restrict__ bias,
    float* __restrict__ OUT, int N)
{
    int gw   = (blockIdx.x * blockDim.x + threadIdx.x) >> 5;
    int lane = threadIdx.x & 31;
    if (gw >= N) return;
    int s0 = g_off[gw], s1 = g_off[gw + 1];
    float di = g_dinv[gw];

    uint2 raw = *(const uint2*)&H[(size_t)gw * HDIM + lane * 4];   // self (4 fp16)
    float2 p01 = __half22float2(*(__half2*)&raw.x);
    float2 p23 = __half22float2(*(__half2*)&raw.y);
    float4 acc = make_float4(p01.x * di, p01.y * di, p23.x * di, p23.y * di);

    for (int j = s0; j < s1; j++) {
        int s = g_csr[j];
        float ds = __ldg(&g_dinv[s]);
        uint2 rv = __ldg((const uint2*)&H[(size_t)s * HDIM + lane * 4]);
        float2 v01 = __half22float2(*(__half2*)&rv.x);
        float2 v23 = __half22float2(*(__half2*)&rv.y);
        acc.x = fmaf(v01.x, ds, acc.x); acc.y = fmaf(v01.y, ds, acc.y);
        acc.z = fmaf(v23.x, ds, acc.z); acc.w = fmaf(v23.y, ds, acc.w);
    }
    float4 bb = *(const float4*)&bias[lane * 4];
    acc.x = acc.x * di + bb.x; acc.y = acc.y * di + bb.y;
    acc.z = acc.z * di + bb.z; acc.w = acc.w * di + bb.w;
    if (BF16OUT) {
        acc.x = fmaxf(acc.x, 0.f); acc.y = fmaxf(acc.y, 0.f);
        acc.z = fmaxf(acc.z, 0.f); acc.w = fmaxf(acc.w, 0.f);
        split_store4(acc, g_ah, g_al, (size_t)gw * HDIM + lane * 4);
    } else {
        *(float4*)&OUT[(size_t)gw * HDIM + lane * 4] = acc;
    }
}

// ---------------- decode: logits[e] = dot(Z[a], Z[b]), 1 warp/edge -----------
__global__ __launch_bounds__(256) void decode_kernel(
    const float* __restrict__ Z, const int* __restrict__ ea,
    const int* __restrict__ eb, float* __restrict__ out, int EL)
{
    int gw   = (blockIdx.x * blockDim.x + threadIdx.x) >> 5;
    int lane = threadIdx.x & 31;
    if (gw >= EL) return;
    int i = ea[gw], j = eb[gw];
    float4 u = *(const float4*)&Z[(size_t)i * HDIM + lane * 4];
    float4 v = *(const float4*)&Z[(size_t)j * HDIM + lane * 4];
    float p = u.x * v.x + u.y * v.y + u.z * v.z + u.w * v.w;
#pragma unroll
    for (int o = 16; o; o >>= 1) p += __shfl_xor_sync(0xffffffffu, p, o);
    if (lane == 0) out[gw] = p;
}

extern "C" void kernel_launch(void* const* d_in, const int* in_sizes, int n_in,
                              void* d_out, int out_size)
{
    const float* x   = (const float*)d_in[0];
    const int*   ei  = (const int*)d_in[1];
    const int*   eli = (const int*)d_in[2];
    const float* W0  = (const float*)d_in[3];
    const float* b0  = (const float*)d_in[4];
    const float* W1  = (const float*)d_in[5];
    const float* b1  = (const float*)d_in[6];
    const float* W2  = (const float*)d_in[7];
    const float* b2  = (const float*)d_in[8];
    float* logits = (float*)d_out;

    const int N  = in_sizes[0] / 256;   // 50000
    const int E  = in_sizes[1] / 2;     // 320000
    const int EL = in_sizes[2] / 2;     // 200000
    const int* src = ei;
    const int* dst = ei + E;
    const int* la  = eli;
    const int* lb  = eli + EL;

    float *p_feat;
    __half *p_h;
    __nv_bfloat16 *p_ah, *p_al, *p_wh, *p_wl;
    cudaGetSymbolAddress((void**)&p_h,    g_h);
    cudaGetSymbolAddress((void**)&p_feat, g_feat);
    cudaGetSymbolAddress((void**)&p_ah,   g_ah);
    cudaGetSymbolAddress((void**)&p_al,   g_al);
    cudaGetSymbolAddress((void**)&p_wh,   g_wh);
    cudaGetSymbolAddress((void**)&p_wl,   g_wl);

    const int SMEM256 = (2 * 128 * 264 + 4 * 128 * 24) * 2;  // 159744
    const int SMEM128 = (2 * 128 * 136 + 4 * 128 * 24) * 2;  //  94208
    cudaFuncSetAttribute((gemm_mma_kernel<256, true, 1>),
                         cudaFuncAttributeMaxDynamicSharedMemorySize, SMEM256);
    cudaFuncSetAttribute((gemm_mma_kernel<128, false, 2>),
                         cudaFuncAttributeMaxDynamicSharedMemorySize, SMEM128);

    // side stream + events for fork-join (host objects, created once)
    static cudaStream_t s_side = nullptr;
    static cudaEvent_t  s_ev0 = nullptr, s_ev1 = nullptr;
    if (s_side == nullptr) {
        cudaStreamCreateWithFlags(&s_side, cudaStreamNonBlocking);
        cudaEventCreateWithFlags(&s_ev0, cudaEventDisableTiming);
        cudaEventCreateWithFlags(&s_ev1, cudaEventDisableTiming);
    }

    const int TB = 256;
    const int nscan      = (N + 255) / 256;
    const int mtiles     = (N + 127) / 128;
    const int agg_blocks = (N + 7) / 8;

    // ---- fork: side branch builds degrees + CSR + dinv ----
    cudaEventRecord(s_ev0, 0);
    cudaStreamWaitEvent(s_side, s_ev0, 0);
    deg_init_kernel<<<(N + TB - 1) / TB, TB, 0, s_side>>>(N);
    deg_count_kernel<<<512, TB, 0, s_side>>>(dst, E);
    scan_block_kernel<<<nscan, 256, 0, s_side>>>(N);
    scan_add_kernel<<<nscan, 256, 0, s_side>>>(N, E, nscan);
    csr_fill_kernel<<<512, TB, 0, s_side>>>(src, dst, E);
    cudaEventRecord(s_ev1, s_side);

    // ---- main branch: W split + layer-0 GEMM (no dinv dependency) ----
    convw_kernel<<<(65536 + TB - 1) / TB, TB>>>(W0, W1, W2);
    gemm_mma_kernel<256, true, 1><<<mtiles, TB, SMEM256>>>(
        nullptr, nullptr, x, p_wh, p_wl, p_h, N);

    // ---- join ----
    cudaStreamWaitEvent(0, s_ev1, 0);

    agg_fin_kernel<true><<<agg_blocks, TB>>>(p_h, b0, nullptr, N);

    // Layer 1: K=128
    gemm_mma_kernel<128, false, 2><<<mtiles, TB, SMEM128>>>(
        p_ah, p_al, nullptr, p_wh + 32768, p_wl + 32768, p_h, N);
    agg_fin_kernel<true><<<agg_blocks, TB>>>(p_h, b1, nullptr, N);

    // Layer 2: K=128, no relu, fp32 out
    gemm_mma_kernel<128, false, 2><<<mtiles, TB, SMEM128>>>(
        p_ah, p_al, nullptr, p_wh + 49152, p_wl + 49152, p_h, N);
    agg_fin_kernel<false><<<agg_blocks, TB>>>(p_h, b2, p_feat, N);

    // Decode
    decode_kernel<<<(EL + 7) / 8, TB>>>(p_feat, la, lb, logits, EL);
}

// round 13
// speedup vs baseline: 1.7064x; 1.0054x over previous
#include <cuda_runtime.h>
#include <cuda_bf16.h>
#include <cuda_fp16.h>
#include <math.h>
#include <stdint.h>

#define NND 50000
#define EMAX 320000
#define HDIM 128

// ---------------- scratch (device globals; allocation-free contract) --------
__device__ int            g_deg[NND];
__device__ float          g_dinv[NND];
__device__ __half         g_h[(size_t)NND * HDIM];     // fp16 message buffer
__device__ __half         g_z[(size_t)NND * HDIM];     // final z (fp16)
__device__ __nv_bfloat16  g_ah[(size_t)NND * HDIM];
__device__ __nv_bfloat16  g_al[(size_t)NND * HDIM];
// W0 at [0, 32768), W1 at [32768, 49152), W2 at [49152, 65536)
__device__ __nv_bfloat16  g_wh[65536];
__device__ __nv_bfloat16  g_wl[65536];
// CSR
__device__ int g_off[NND + 1];
__device__ int g_cur[NND];
__device__ int g_csr[EMAX];
__device__ int g_part[256];

// ---------------- W split (main branch) --------------------------------------
__global__ void convw_kernel(const float* __restrict__ W0,
                             const float* __restrict__ W1,
                             const float* __restrict__ W2) {
    int j = blockIdx.x * blockDim.x + threadIdx.x;
    if (j >= 65536) return;
    const float* W; int K, jj = j;
    if (j < 32768)      { W = W0; K = 256; }
    else if (j < 49152) { W = W1; K = 128; jj -= 32768; }
    else                { W = W2; K = 128; jj -= 49152; }
    int nn = jj / K, k = jj % K;
    float v = W[k * 128 + nn];
    float h = __bfloat162float(__float2bfloat16(v));
    g_wh[j] = __float2bfloat16(h);
    g_wl[j] = __float2bfloat16(v - h);
}

// ---------------- degree / CSR (side branch) ----------------------------------
__global__ void deg_init_kernel(int n) {
    int i = blockIdx.x * blockDim.x + threadIdx.x;
    if (i < n) g_deg[i] = 1;  // self-loop
}
__global__ void deg_count_kernel(const int* __restrict__ dst, int E) {
    for (int e = blockIdx.x * blockDim.x + threadIdx.x; e < E;
         e += gridDim.x * blockDim.x)
        atomicAdd(&g_deg[dst[e]], 1);
}
__global__ void scan_block_kernel(int n) {
    __shared__ int sh[256];
    int i = blockIdx.x * 256 + threadIdx.x;
    int v = (i < n) ? g_deg[i] - 1 : 0;
    sh[threadIdx.x] = v;
    __syncthreads();
#pragma unroll
    for (int o = 1; o < 256; o <<= 1) {
        int t = (threadIdx.x >= o) ? sh[threadIdx.x - o] : 0;
        __syncthreads();
        sh[threadIdx.x] += t;
        __syncthreads();
    }
    int incl = sh[threadIdx.x];
    if (i < n) g_off[i] = incl - v;                 // block-local exclusive
    if (threadIdx.x == 255) g_part[blockIdx.x] = incl;
}
// block offset: warp 0 reduces g_part[j < bid]; +dinv fused
__global__ void scan_add_kernel(int n, int E, int nb) {
    __shared__ int s_boff;
    int t = threadIdx.x, bid = blockIdx.x;
    if (t < 32) {
        int acc = 0;
        for (int j = t; j < bid; j += 32) acc += g_part[j];
#pragma unroll
        for (int o = 16; o; o >>= 1) acc += __shfl_xor_sync(0xffffffffu, acc, o);
        if (t == 0) s_boff = acc;
    }
    __syncthreads();
    int i = bid * 256 + t;
    if (i < n) {
        int o = g_off[i] + s_boff;
        g_off[i] = o;
        g_cur[i] = o;
        g_dinv[i] = rsqrtf((float)g_deg[i]);
    }
    if (i == 0) g_off[n] = E;
}
__global__ void csr_fill_kernel(const int* __restrict__ src,
                                const int* __restrict__ dst, int E) {
    for (int e = blockIdx.x * blockDim.x + threadIdx.x; e < E;
         e += gridDim.x * blockDim.x) {
        int p = atomicAdd(&g_cur[dst[e]], 1);
        g_csr[p] = src[e];
    }
}

// ---------------- bf16 split helpers ----------------
__device__ __forceinline__ void split_store4(float4 v, __nv_bfloat16* ah,
                                             __nv_bfloat16* al, size_t off) {
    float hx = __bfloat162float(__float2bfloat16(v.x));
    float hy = __bfloat162float(__float2bfloat16(v.y));
    float hz = __bfloat162float(__float2bfloat16(v.z));
    float hw = __bfloat162float(__float2bfloat16(v.w));
    __nv_bfloat162 h01 = __floats2bfloat162_rn(hx, hy);
    __nv_bfloat162 h23 = __floats2bfloat162_rn(hz, hw);
    __nv_bfloat162 l01 = __floats2bfloat162_rn(v.x - hx, v.y - hy);
    __nv_bfloat162 l23 = __floats2bfloat162_rn(v.z - hz, v.w - hw);
    uint2 hp, lp;
    hp.x = *(uint32_t*)&h01; hp.y = *(uint32_t*)&h23;
    lp.x = *(uint32_t*)&l01; lp.y = *(uint32_t*)&l23;
    *(uint2*)&ah[off] = hp;
    *(uint2*)&al[off] = lp;
}

// ---------------- HMMA GEMM: H(fp16) = A @ W^T  (bf16x3 split, raw) ----------
#define MMA16816(d, a, b) \
    asm volatile( \
        "mma.sync.aligned.m16n8k16.row.col.f32.bf16.bf16.f32 " \
        "{%0,%1,%2,%3}, {%4,%5,%6,%7}, {%8,%9}, {%0,%1,%2,%3};" \
        : "+f"((d)[0]), "+f"((d)[1]), "+f"((d)[2]), "+f"((d)[3]) \
        : "r"((a)[0]), "r"((a)[1]), "r"((a)[2]), "r"((a)[3]), \
          "r"((b)[0]), "r"((b)[1]))

// FUSE=true: A comes from fp32 Xf (split to hi/lo in registers during copy).
template <int K, bool FUSE, int MINBLK>
__global__ __launch_bounds__(256, MINBLK) void gemm_mma_kernel(
    const __nv_bfloat16* __restrict__ Ah, const __nv_bfloat16* __restrict__ Al,
    const float* __restrict__ Xf,
    const __nv_bfloat16* __restrict__ Wh, const __nv_bfloat16* __restrict__ Wl,
    __half* __restrict__ H, int M)
{
    extern __shared__ char smem[];
    const int PW = K + 8;   // W row pitch (bf16)
    const int PA = 24;      // A row pitch (bf16)

    __nv_bfloat16* sWh = (__nv_bfloat16*)smem;
    __nv_bfloat16* sWl = sWh + 128 * PW;
    __nv_bfloat16* sA  = sWl + 128 * PW;   // [stage][buf][128][PA]

    const int tid = threadIdx.x, lane = tid & 31, wid = tid >> 5;
    const int wm = wid & 3, wn = wid >> 2;     // warp tile: 32 rows x 64 cols
    const int m0 = blockIdx.x * 128;

    const int WCH = 128 * (K / 8);
    for (int i = tid; i < WCH; i += 256) {
        int n = i / (K / 8), c = i % (K / 8);
        *(uint4*)(sWh + n * PW + c * 8) = *(const uint4*)(Wh + n * K + c * 8);
        *(uint4*)(sWl + n * PW + c * 8) = *(const uint4*)(Wl + n * K + c * 8);
    }

    auto copyA = [&](int ks, int st) {
        if (FUSE) {
            int row = tid >> 1, half = tid & 1;
            int gr = m0 + row;
            float4 v0 = make_float4(0.f, 0.f, 0.f, 0.f), v1 = v0;
            if (gr < M) {
                const float4* p = (const float4*)(Xf + (size_t)gr * K + ks * 16 + half * 8);
                v0 = p[0]; v1 = p[1];
            }
            float f[8] = {v0.x, v0.y, v0.z, v0.w, v1.x, v1.y, v1.z, v1.w};
            uint32_t hi[4], lo[4];
#pragma unroll
            for (int j = 0; j < 4; j++) {
                float a = f[2 * j], b = f[2 * j + 1];
                float ha = __bfloat162float(__float2bfloat16(a));
                float hb = __bfloat162float(__float2bfloat16(b));
                __nv_bfloat162 hh = __floats2bfloat162_rn(ha, hb);
                __nv_bfloat162 ll = __floats2bfloat162_rn(a - ha, b - hb);
                hi[j] = *(uint32_t*)&hh;
                lo[j] = *(uint32_t*)&ll;
            }
            __nv_bfloat16* dh = sA + ((st * 2 + 0) * 128 + row) * PA + half * 8;
            __nv_bfloat16* dl = sA + ((st * 2 + 1) * 128 + row) * PA + half * 8;
            *(uint4*)dh = make_uint4(hi[0], hi[1], hi[2], hi[3]);
            *(uint4*)dl = make_uint4(lo[0], lo[1], lo[2], lo[3]);
        } else {
            int buf = tid >> 7, row = tid & 127;
            int gr = m0 + row;
            const __nv_bfloat16* src = buf ? Al : Ah;
            uint4 v0 = make_uint4(0u, 0u, 0u, 0u), v1 = v0;
            if (gr < M) {
                const uint4* p = (const uint4*)(src + (size_t)gr * K + ks * 16);
                v0 = p[0]; v1 = p[1];
            }
            __nv_bfloat16* d = sA + ((st * 2 + buf) * 128 + row) * PA;
            *(uint4*)d = v0; *(uint4*)(d + 8) = v1;
        }
    };

    float acc[2][8][4];
#pragma unroll
    for (int mt = 0; mt < 2; mt++)
#pragma unroll
        for (int nt = 0; nt < 8; nt++)
#pragma unroll
            for (int j = 0; j < 4; j++) acc[mt][nt][j] = 0.f;

    const int NS = K / 16;
    copyA(0, 0);
    __syncthreads();

    const int ar0 = wm * 32 + (lane >> 2);
    const int kk  = (lane & 3) * 2;
    const int nb  = wn * 64 + (lane >> 2);

    for (int ks = 0; ks < NS; ks++) {
        int st = ks & 1;
        if (ks + 1 < NS) copyA(ks + 1, st ^ 1);

        const __nv_bfloat16* Abh = sA + (st * 2 + 0) * 128 * PA;
        const __nv_bfloat16* Abl = sA + (st * 2 + 1) * 128 * PA;

        uint32_t ah[2][4], al[2][4];
#pragma unroll
        for (int mt = 0; mt < 2; mt++) {
            int r = ar0 + mt * 16;
            ah[mt][0] = *(const uint32_t*)(Abh + r * PA + kk);
            ah[mt][1] = *(const uint32_t*)(Abh + (r + 8) * PA + kk);
            ah[mt][2] = *(const uint32_t*)(Abh + r * PA + kk + 8);
            ah[mt][3] = *(const uint32_t*)(Abh + (r + 8) * PA + kk + 8);
            al[mt][0] = *(const uint32_t*)(Abl + r * PA + kk);
            al[mt][1] = *(const uint32_t*)(Abl + (r + 8) * PA + kk);
            al[mt][2] = *(const uint32_t*)(Abl + r * PA + kk + 8);
            al[mt][3] = *(const uint32_t*)(Abl + (r + 8) * PA + kk + 8);
        }
        uint32_t bh[8][2], bl[8][2];
        int kw = ks * 16 + kk;
#pragma unroll
        for (int nt = 0; nt < 8; nt++) {
            const __nv_bfloat16* ph = sWh + (nb + nt * 8) * PW + kw;
            const __nv_bfloat16* pl = sWl + (nb + nt * 8) * PW + kw;
            bh[nt][0] = *(const uint32_t*)ph;
            bh[nt][1] = *(const uint32_t*)(ph + 8);
            bl[nt][0] = *(const uint32_t*)pl;
            bl[nt][1] = *(const uint32_t*)(pl + 8);
        }
#pragma unroll
        for (int mt = 0; mt < 2; mt++)
#pragma unroll
            for (int nt = 0; nt < 8; nt++) {
                MMA16816(acc[mt][nt], ah[mt], bh[nt]);  // hi*hi
                MMA16816(acc[mt][nt], ah[mt], bl[nt]);  // hi*lo
                MMA16816(acc[mt][nt], al[mt], bh[nt]);  // lo*hi
            }
        __syncthreads();
    }

    // ---- epilogue: write raw H as fp16 ----
    const int cbase = wn * 64 + (lane & 3) * 2;
#pragma unroll
    for (int mt = 0; mt < 2; mt++) {
        int ra = m0 + wm * 32 + mt * 16 + (lane >> 2);
        int rb = ra + 8;
#pragma unroll
        for (int nt = 0; nt < 8; nt++) {
            int col = cbase + nt * 8;
            if (ra < M)
                *(__half2*)&H[(size_t)ra * HDIM + col] =
                    __floats2half2_rn(acc[mt][nt][0], acc[mt][nt][1]);
            if (rb < M)
                *(__half2*)&H[(size_t)rb * HDIM + col] =
                    __floats2half2_rn(acc[mt][nt][2], acc[mt][nt][3]);
        }
    }
}

// ---------------- fused aggregate + finalize (fp16 msgs, 4x pipelined) -------
// inner = dinv[d]*H[d] + sum_s dinv[s]*H[s];  out = inner*dinv[d] + b; [relu]
// BF16OUT: relu + bf16 hi/lo split -> g_ah/g_al.  else: fp16 z -> OUT.
__device__ __forceinline__ void acc_row(float4& acc, uint2 rv, float ds) {
    float2 v01 = __half22float2(*(__half2*)&rv.x);
    float2 v23 = __half22float2(*(__half2*)&rv.y);
    acc.x = fmaf(v01.x, ds, acc.x); acc.y = fmaf(v01.y, ds, acc.y);
    acc.z = fmaf(v23.x, ds, acc.z); acc.w = fmaf(v23.y, ds, acc.w);
}
template <bool BF16OUT>
__global__ __launch_bounds__(256) void agg_fin_kernel(
    const __half* __restrict__ H, const float* __restrict__ bias,
    __half* __restrict__ OUT, int N)
{
    int gw   = (blockIdx.x * blockDim.x + threadIdx.x) >> 5;
    int lane = threadIdx.x & 31;
    if (gw >= N) return;
    int s0 = g_off[gw], s1 = g_off[gw + 1];
    float di = g_dinv[gw];

    uint2 raw = *(const uint2*)&H[(size_t)gw * HDIM + lane * 4];   // self
    float2 p01 = __half22float2(*(__half2*)&raw.x);
    float2 p23 = __half22float2(*(__half2*)&raw.y);
    float4 acc = make_float4(p01.x * di, p01.y * di, p23.x * di, p23.y * di);

    int j = s0;
    for (; j + 4 <= s1; j += 4) {                  // 4x software pipeline
        int sa = g_csr[j],     sb = g_csr[j + 1];
        int sc = g_csr[j + 2], sd = g_csr[j + 3];
        float da = __ldg(&g_dinv[sa]), db = __ldg(&g_dinv[sb]);
        float dc = __ldg(&g_dinv[sc]), dd = __ldg(&g_dinv[sd]);
        uint2 ra = __ldg((const uint2*)&H[(size_t)sa * HDIM + lane * 4]);
        uint2 rb = __ldg((const uint2*)&H[(size_t)sb * HDIM + lane * 4]);
        uint2 rc = __ldg((const uint2*)&H[(size_t)sc * HDIM + lane * 4]);
        uint2 rd = __ldg((const uint2*)&H[(size_t)sd * HDIM + lane * 4]);
        acc_row(acc, ra, da); acc_row(acc, rb, db);
        acc_row(acc, rc, dc); acc_row(acc, rd, dd);
    }
    for (; j < s1; j++) {
        int s = g_csr[j];
        float ds = __ldg(&g_dinv[s]);
        uint2 rv = __ldg((const uint2*)&H[(size_t)s * HDIM + lane * 4]);
        acc_row(acc, rv, ds);
    }

    float4 bb = *(const float4*)&bias[lane * 4];
    acc.x = acc.x * di + bb.x; acc.y = acc.y * di + bb.y;
    acc.z = acc.z * di + bb.z; acc.w = acc.w * di + bb.w;
    if (BF16OUT) {
        acc.x = fmaxf(acc.x, 0.f); acc.y = fmaxf(acc.y, 0.f);
        acc.z = fmaxf(acc.z, 0.f); acc.w = fmaxf(acc.w, 0.f);
        split_store4(acc, g_ah, g_al, (size_t)gw * HDIM + lane * 4);
    } else {
        uint2 o;
        *(__half2*)&o.x = __floats2half2_rn(acc.x, acc.y);
        *(__half2*)&o.y = __floats2half2_rn(acc.z, acc.w);
        *(uint2*)&OUT[(size_t)gw * HDIM + lane * 4] = o;
    }
}

// ---------------- decode: logits[e] = dot(Z[a], Z[b]), fp16 z, 1 warp/edge ---
__global__ __launch_bounds__(256) void decode_kernel(
    const __half* __restrict__ Z, const int* __restrict__ ea,
    const int* __restrict__ eb, float* __restrict__ out, int EL)
{
    int gw   = (blockIdx.x * blockDim.x + threadIdx.x) >> 5;
    int lane = threadIdx.x & 31;
    if (gw >= EL) return;
    int i = ea[gw], j = eb[gw];
    uint2 ru = __ldg((const uint2*)&Z[(size_t)i * HDIM + lane * 4]);
    uint2 rv = __ldg((const uint2*)&Z[(size_t)j * HDIM + lane * 4]);
    float2 u01 = __half22float2(*(__half2*)&ru.x);
    float2 u23 = __half22float2(*(__half2*)&ru.y);
    float2 v01 = __half22float2(*(__half2*)&rv.x);
    float2 v23 = __half22float2(*(__half2*)&rv.y);
    float p = u01.x * v01.x + u01.y * v01.y + u23.x * v23.x + u23.y * v23.y;
#pragma unroll
    for (int o = 16; o; o >>= 1) p += __shfl_xor_sync(0xffffffffu, p, o);
    if (lane == 0) out[gw] = p;
}

extern "C" void kernel_launch(void* const* d_in, const int* in_sizes, int n_in,
                              void* d_out, int out_size)
{
    const float* x   = (const float*)d_in[0];
    const int*   ei  = (const int*)d_in[1];
    const int*   eli = (const int*)d_in[2];
    const float* W0  = (const float*)d_in[3];
    const float* b0  = (const float*)d_in[4];
    const float* W1  = (const float*)d_in[5];
    const float* b1  = (const float*)d_in[6];
    const float* W2  = (const float*)d_in[7];
    const float* b2  = (const float*)d_in[8];
    float* logits = (float*)d_out;

    const int N  = in_sizes[0] / 256;   // 50000
    const int E  = in_sizes[1] / 2;     // 320000
    const int EL = in_sizes[2] / 2;     // 200000
    const int* src = ei;
    const int* dst = ei + E;
    const int* la  = eli;
    const int* lb  = eli + EL;

    __half *p_h, *p_z;
    __nv_bfloat16 *p_ah, *p_al, *p_wh, *p_wl;
    cudaGetSymbolAddress((void**)&p_h,  g_h);
    cudaGetSymbolAddress((void**)&p_z,  g_z);
    cudaGetSymbolAddress((void**)&p_ah, g_ah);
    cudaGetSymbolAddress((void**)&p_al, g_al);
    cudaGetSymbolAddress((void**)&p_wh, g_wh);
    cudaGetSymbolAddress((void**)&p_wl, g_wl);

    const int SMEM256 = (2 * 128 * 264 + 4 * 128 * 24) * 2;  // 159744
    const int SMEM128 = (2 * 128 * 136 + 4 * 128 * 24) * 2;  //  94208
    cudaFuncSetAttribute((gemm_mma_kernel<256, true, 1>),
                         cudaFuncAttributeMaxDynamicSharedMemorySize, SMEM256);
    cudaFuncSetAttribute((gemm_mma_kernel<128, false, 2>),
                         cudaFuncAttributeMaxDynamicSharedMemorySize, SMEM128);

    // side stream + events for fork-join (host objects, created once)
    static cudaStream_t s_side = nullptr;
    static cudaEvent_t  s_ev0 = nullptr, s_ev1 = nullptr;
    if (s_side == nullptr) {
        cudaStreamCreateWithFlags(&s_side, cudaStreamNonBlocking);
        cudaEventCreateWithFlags(&s_ev0, cudaEventDisableTiming);
        cudaEventCreateWithFlags(&s_ev1, cudaEventDisableTiming);
    }

    const int TB = 256;
    const int nscan      = (N + 255) / 256;
    const int mtiles     = (N + 127) / 128;
    const int agg_blocks = (N + 7) / 8;

    // ---- fork: side branch builds degrees + CSR + dinv ----
    cudaEventRecord(s_ev0, 0);
    cudaStreamWaitEvent(s_side, s_ev0, 0);
    deg_init_kernel<<<(N + TB - 1) / TB, TB, 0, s_side>>>(N);
    deg_count_kernel<<<512, TB, 0, s_side>>>(dst, E);
    scan_block_kernel<<<nscan, 256, 0, s_side>>>(N);
    scan_add_kernel<<<nscan, 256, 0, s_side>>>(N, E, nscan);
    csr_fill_kernel<<<512, TB, 0, s_side>>>(src, dst, E);
    cudaEventRecord(s_ev1, s_side);

    // ---- main branch: W split + layer-0 GEMM (no dinv dependency) ----
    convw_kernel<<<(65536 + TB - 1) / TB, TB>>>(W0, W1, W2);
    gemm_mma_kernel<256, true, 1><<<mtiles, TB, SMEM256>>>(
        nullptr, nullptr, x, p_wh, p_wl, p_h, N);

    // ---- join ----
    cudaStreamWaitEvent(0, s_ev1, 0);

    agg_fin_kernel<true><<<agg_blocks, TB>>>(p_h, b0, nullptr, N);

    // Layer 1: K=128
    gemm_mma_kernel<128, false, 2><<<mtiles, TB, SMEM128>>>(
        p_ah, p_al, nullptr, p_wh + 32768, p_wl + 32768, p_h, N);
    agg_fin_kernel<true><<<agg_blocks, TB>>>(p_h, b1, nullptr, N);

    // Layer 2: K=128, no relu, fp16 z out
    gemm_mma_kernel<128, false, 2><<<mtiles, TB, SMEM128>>>(
        p_ah, p_al, nullptr, p_wh + 49152, p_wl + 49152, p_h, N);
    agg_fin_kernel<false><<<agg_blocks, TB>>>(p_h, b2, p_z, N);

    // Decode
    decode_kernel<<<(EL + 7) / 8, TB>>>(p_z, la, lb, logits, EL);
}